// round 14
// baseline (speedup 1.0000x reference)
#include <cuda_runtime.h>
#include <cuda_bf16.h>
#include <math.h>
#include <stdint.h>

// Problem constants
#define BB   4
#define CINE 256
#define CIN  1024
#define CO   256
#define HW   16384        // H*W = 128*128
#define CQ   32
#define NPOS 16384.0f

// GEMM smem layout (bytes).
// A: [buf][half][128 rows][80B], B: [buf][plane][32 rows][272B]
#define YSA      0
#define YSA_HALF 10240
#define YSA_BUF  20480
#define YSB      40960
#define YSB_PL   8704
#define YSB_BUF  17408
#define YTOT     75776

// Scratch (device globals -- no runtime allocation allowed)
__device__ float g_x[(size_t)BB * CO * HW];   // raw conv output (pre-BN)
__device__ float g_v[(size_t)BB * CO * HW];   // V
__device__ float g_q[BB * CQ * HW];           // Q then Qn
__device__ float g_k[BB * CQ * HW];           // K then Kn
__device__ float g_mean[CO];
__device__ float g_invstd[CO];
__device__ float g_ksum[BB * CQ];
__device__ float g_vsum[BB * CO];
__device__ float g_matrix[BB * CQ * CO];
// pre-split weights (bf16 hi/lo)
__device__ __nv_bfloat16 g_wc_h[CO * CIN], g_wc_l[CO * CIN];
__device__ __nv_bfloat16 g_wq_h[384 * CO], g_wq_l[384 * CO];   // rows 320..383 zero
// pre-split inputs (concatenated, [b][c][n]) and feat
__device__ __nv_bfloat16 g_bh[(size_t)BB * CIN * HW], g_bl[(size_t)BB * CIN * HW];
__device__ __nv_bfloat16 g_fh[(size_t)BB * CO * HW],  g_fl[(size_t)BB * CO * HW];

__device__ __forceinline__ float fixnum(float r) {
    if (isnan(r)) return 0.0f;
    if (isinf(r)) return r > 0.0f ? 1.0f : -1.0f;
    return r;
}

__device__ __forceinline__ uint32_t smem_u32(const void* p) {
    uint32_t a;
    asm("{ .reg .u64 t; cvta.to.shared.u64 t, %1; cvt.u32.u64 %0, t; }"
        : "=r"(a) : "l"(p));
    return a;
}

#define CP_ASYNC(dst, src) \
    asm volatile("cp.async.cg.shared.global [%0], [%1], 16;" :: "r"(dst), "l"(src))
#define CP_COMMIT() asm volatile("cp.async.commit_group;" ::: "memory")
#define CP_WAIT0()  asm volatile("cp.async.wait_group 0;" ::: "memory")

__device__ __forceinline__ void ldm_x4(uint32_t& r0, uint32_t& r1,
                                       uint32_t& r2, uint32_t& r3, uint32_t addr) {
    asm volatile("ldmatrix.sync.aligned.m8n8.x4.shared.b16 {%0,%1,%2,%3}, [%4];"
                 : "=r"(r0), "=r"(r1), "=r"(r2), "=r"(r3) : "r"(addr));
}
__device__ __forceinline__ void ldm_x4t(uint32_t& r0, uint32_t& r1,
                                        uint32_t& r2, uint32_t& r3, uint32_t addr) {
    asm volatile("ldmatrix.sync.aligned.m8n8.x4.trans.shared.b16 {%0,%1,%2,%3}, [%4];"
                 : "=r"(r0), "=r"(r1), "=r"(r2), "=r"(r3) : "r"(addr));
}

// hi/lo bf16 split of two floats, packed as bf16x2 (x -> low 16 bits)
__device__ __forceinline__ void split_pack(float x, float y, uint32_t& h, uint32_t& l) {
    __nv_bfloat162 hb = __floats2bfloat162_rn(x, y);
    h = *reinterpret_cast<uint32_t*>(&hb);
    float rx = x - __bfloat162float(hb.x);
    float ry = y - __bfloat162float(hb.y);
    __nv_bfloat162 lb = __floats2bfloat162_rn(rx, ry);
    l = *reinterpret_cast<uint32_t*>(&lb);
}

// m16n8k16 row.col bf16 MMA, f32 accumulate in-place
__device__ __forceinline__ void mma16816(float* c,
    uint32_t a0, uint32_t a1, uint32_t a2, uint32_t a3,
    uint32_t b0, uint32_t b1)
{
    asm volatile(
        "mma.sync.aligned.m16n8k16.row.col.f32.bf16.bf16.f32 "
        "{%0,%1,%2,%3}, {%4,%5,%6,%7}, {%8,%9}, {%0,%1,%2,%3};"
        : "+f"(c[0]), "+f"(c[1]), "+f"(c[2]), "+f"(c[3])
        : "r"(a0), "r"(a1), "r"(a2), "r"(a3), "r"(b0), "r"(b1));
}

// ---------------------------------------------------------------------------
__global__ void zero_kernel() {
    int tid = blockIdx.x * blockDim.x + threadIdx.x;
    int total = BB * CQ + BB * CQ * CO + BB * CO;
    for (int i = tid; i < total; i += gridDim.x * blockDim.x) {
        if (i < BB * CQ) g_ksum[i] = 0.0f;
        else if (i < BB * CQ + BB * CQ * CO) g_matrix[i - BB * CQ] = 0.0f;
        else g_vsum[i - BB * CQ - BB * CQ * CO] = 0.0f;
    }
}

// ---------------------------------------------------------------------------
// Pre-split all weights to bf16 hi/lo.
__global__ __launch_bounds__(256) void convert_weights(
    const float* __restrict__ w,
    const float* __restrict__ wq, const float* __restrict__ wk,
    const float* __restrict__ wv)
{
    int idx = blockIdx.x * 256 + threadIdx.x;
    if (idx < CO * CIN) {
        float f = w[idx];
        __nv_bfloat16 h = __float2bfloat16_rn(f);
        g_wc_h[idx] = h;
        g_wc_l[idx] = __float2bfloat16_rn(f - __bfloat162float(h));
    } else {
        int j = idx - CO * CIN;
        if (j < 384 * CO) {
            int row = j >> 8, k = j & 255;
            float f = (row < 32)  ? wq[row * CO + k]
                    : (row < 64)  ? wk[(row - 32) * CO + k]
                    : (row < 320) ? wv[(row - 64) * CO + k] : 0.0f;
            __nv_bfloat16 h = __float2bfloat16_rn(f);
            g_wq_h[j] = h;
            g_wq_l[j] = __float2bfloat16_rn(f - __bfloat162float(h));
        }
    }
}

// ---------------------------------------------------------------------------
// Pre-split concatenated inputs to bf16 hi/lo planes (elementwise, BW-bound).
__global__ __launch_bounds__(256) void convert_inputs(
    const float* __restrict__ s5, const float* __restrict__ s4,
    const float* __restrict__ s3, const float* __restrict__ s2)
{
    size_t idx4 = (size_t)blockIdx.x * 256 + threadIdx.x;   // float4 index
    int n4 = (int)(idx4 & 4095);                            // HW/4 = 4096
    size_t rest = idx4 >> 12;
    int c = (int)(rest & (CIN - 1));
    int b = (int)(rest >> 10);
    const float* src = (c < 512) ? (c < 256 ? s5 : s4) : (c < 768 ? s3 : s2);
    float4 v = ((const float4*)src)[(size_t)(b * CINE + (c & 255)) * 4096 + n4];
    uint32_t h0, l0, h1, l1;
    split_pack(v.x, v.y, h0, l0);
    split_pack(v.z, v.w, h1, l1);
    ((uint2*)g_bh)[idx4] = make_uint2(h0, h1);
    ((uint2*)g_bl)[idx4] = make_uint2(l0, l1);
}

// ---------------------------------------------------------------------------
// BN + ReLU + split feat to bf16 hi/lo planes.
__global__ __launch_bounds__(256) void convert_feat(
    const float* __restrict__ bn_gamma, const float* __restrict__ bn_beta)
{
    size_t idx4 = (size_t)blockIdx.x * 256 + threadIdx.x;
    int c = (int)((idx4 >> 12) & (CO - 1));
    float sc = g_invstd[c] * bn_gamma[c];
    float sf = bn_beta[c] - g_mean[c] * sc;
    float4 v = ((const float4*)g_x)[idx4];
    v.x = fmaxf(v.x * sc + sf, 0.0f);
    v.y = fmaxf(v.y * sc + sf, 0.0f);
    v.z = fmaxf(v.z * sc + sf, 0.0f);
    v.w = fmaxf(v.w * sc + sf, 0.0f);
    uint32_t h0, l0, h1, l1;
    split_pack(v.x, v.y, h0, l0);
    split_pack(v.z, v.w, h1, l1);
    ((uint2*)g_fh)[idx4] = make_uint2(h0, h1);
    ((uint2*)g_fl)[idx4] = make_uint2(l0, l1);
}

// ---------------------------------------------------------------------------
// conv 1x1: g_x[b,m,n] = sum_c w[m,c]*fcat[b,c,n]. CTA 128x128, k-chunk 32,
// 4 warps of 64x64. All operands pre-split bf16: loop = cp.async + ldm + mma.
__global__ __launch_bounds__(128, 2) void conv_gemm_mma()
{
    extern __shared__ char smem[];
    const uint32_t sb = smem_u32(smem);

    const int t = threadIdx.x;
    const int wid = t >> 5, lane = t & 31;
    const int g = lane >> 2, tg = lane & 3;
    const int b = blockIdx.z, m0 = blockIdx.y * 128, n0 = blockIdx.x * 128;
    const int wm = (wid & 1) * 64, wn = (wid >> 1) * 64;

    uint32_t aA[4];
#pragma unroll
    for (int mt = 0; mt < 4; mt++)
        aA[mt] = sb + YSA + (uint32_t)((wm + mt * 16 + (lane & 15)) * 80 + (lane >> 4) * 16);
    uint32_t aB[4];
#pragma unroll
    for (int p = 0; p < 4; p++)
        aB[p] = sb + YSB + (uint32_t)((lane & 15) * 272 + (wn + p * 16 + (lane >> 4) * 8) * 2);

    float acc[4][8][4];
#pragma unroll
    for (int i = 0; i < 4; i++)
#pragma unroll
        for (int j = 0; j < 8; j++)
#pragma unroll
            for (int r = 0; r < 4; r++) acc[i][j][r] = 0.0f;

    auto issue = [&](int buf, int k0) {
#pragma unroll
        for (int i = 0; i < 8; i++) {        // A: 1024 chunks [half][row 128][4x16B]
            int id = t + i * 128;
            int half = id >> 9, id2 = id & 511, row = id2 >> 2, cs = id2 & 3;
            const __nv_bfloat16* src = (half ? g_wc_l : g_wc_h)
                + (size_t)(m0 + row) * CIN + k0 + cs * 8;
            CP_ASYNC(sb + YSA + buf * YSA_BUF + half * YSA_HALF + row * 80 + cs * 16, src);
        }
#pragma unroll
        for (int i = 0; i < 8; i++) {        // B: 1024 chunks [plane][k 32][16x16B]
            int id = t + i * 128;
            int plane = id >> 9, id2 = id & 511, row = id2 >> 4, c = id2 & 15;
            const __nv_bfloat16* src = (plane ? g_bl : g_bh)
                + (size_t)(b * CIN + k0 + row) * HW + n0 + c * 8;
            CP_ASYNC(sb + YSB + buf * YSB_BUF + plane * YSB_PL + row * 272 + c * 16, src);
        }
    };

    issue(0, 0); CP_COMMIT();
    const int NI = CIN / 32;
    for (int it = 0; it < NI; it++) {
        const int buf = it & 1;
        CP_WAIT0();
        __syncthreads();
        if (it + 1 < NI) { issue(buf ^ 1, (it + 1) * 32); CP_COMMIT(); }

        const uint32_t offA = buf * YSA_BUF, offB = buf * YSB_BUF;
#pragma unroll
        for (int ks = 0; ks < 2; ks++) {
            const uint32_t oA = offA + ks * 32, oB = offB + ks * 4352;
            uint32_t af[4][4], bh[8][2], bl[8][2];
#pragma unroll
            for (int p = 0; p < 4; p++)
                ldm_x4t(bh[2 * p][0], bh[2 * p][1], bh[2 * p + 1][0], bh[2 * p + 1][1],
                        aB[p] + oB);
#pragma unroll
            for (int mt = 0; mt < 4; mt++)
                ldm_x4(af[mt][0], af[mt][1], af[mt][2], af[mt][3], aA[mt] + oA);
#pragma unroll
            for (int mt = 0; mt < 4; mt++)
#pragma unroll
                for (int nt = 0; nt < 8; nt++)
                    mma16816(acc[mt][nt], af[mt][0], af[mt][1], af[mt][2], af[mt][3],
                             bh[nt][0], bh[nt][1]);
#pragma unroll
            for (int p = 0; p < 4; p++)
                ldm_x4t(bl[2 * p][0], bl[2 * p][1], bl[2 * p + 1][0], bl[2 * p + 1][1],
                        aB[p] + oB + YSB_PL);
#pragma unroll
            for (int mt = 0; mt < 4; mt++)
#pragma unroll
                for (int nt = 0; nt < 8; nt++)
                    mma16816(acc[mt][nt], af[mt][0], af[mt][1], af[mt][2], af[mt][3],
                             bl[nt][0], bl[nt][1]);
#pragma unroll
            for (int mt = 0; mt < 4; mt++)
                ldm_x4(af[mt][0], af[mt][1], af[mt][2], af[mt][3], aA[mt] + oA + YSA_HALF);
#pragma unroll
            for (int mt = 0; mt < 4; mt++)
#pragma unroll
                for (int nt = 0; nt < 8; nt++)
                    mma16816(acc[mt][nt], af[mt][0], af[mt][1], af[mt][2], af[mt][3],
                             bh[nt][0], bh[nt][1]);
        }
    }

    // writeback
#pragma unroll
    for (int mt = 0; mt < 4; mt++) {
        int m = m0 + wm + mt * 16 + g;
        float* base = g_x + (size_t)(b * CO + m) * HW + n0 + wn + 2 * tg;
#pragma unroll
        for (int nt = 0; nt < 8; nt++) {
            float* p = base + nt * 8;
            *(float2*)p = make_float2(acc[mt][nt][0], acc[mt][nt][1]);
            *(float2*)(p + 8 * HW) = make_float2(acc[mt][nt][2], acc[mt][nt][3]);
        }
    }
}

// ---------------------------------------------------------------------------
// BN statistics over raw conv output: one block per channel
__global__ __launch_bounds__(512) void bn_stats() {
    const int co = blockIdx.x;
    const int tid = threadIdx.x;
    float s = 0.0f, ss = 0.0f;
    for (int b = 0; b < BB; b++) {
        const float* p = g_x + (size_t)(b * CO + co) * HW;
        for (int i = tid; i < HW; i += 512) {
            float v = p[i];
            s += v;
            ss += v * v;
        }
    }
    __shared__ float rs[512], rss[512];
    rs[tid] = s; rss[tid] = ss;
    __syncthreads();
    for (int off = 256; off > 0; off >>= 1) {
        if (tid < off) { rs[tid] += rs[tid + off]; rss[tid] += rss[tid + off]; }
        __syncthreads();
    }
    if (tid == 0) {
        const float cnt = (float)(BB * HW);
        float mean = rs[0] / cnt;
        float var  = rss[0] / cnt - mean * mean;
        g_mean[co]   = mean;
        g_invstd[co] = rsqrtf(var + 1e-5f);
    }
}

// ---------------------------------------------------------------------------
// QKV GEMM over pre-split feat planes. Same tight loop; fused vsum in epilogue.
// rows 0..31 = Q, 32..63 = K, 64..319 = V.
__global__ __launch_bounds__(128, 2) void qkv_gemm_mma(
    const float* __restrict__ bq, const float* __restrict__ bk,
    const float* __restrict__ bv)
{
    extern __shared__ char smem[];
    const uint32_t sb = smem_u32(smem);

    const int t = threadIdx.x;
    const int wid = t >> 5, lane = t & 31;
    const int g = lane >> 2, tg = lane & 3;
    const int b = blockIdx.z, m0 = blockIdx.y * 128, n0 = blockIdx.x * 128;
    const int wm = (wid & 1) * 64, wn = (wid >> 1) * 64;

    uint32_t aA[4];
#pragma unroll
    for (int mt = 0; mt < 4; mt++)
        aA[mt] = sb + YSA + (uint32_t)((wm + mt * 16 + (lane & 15)) * 80 + (lane >> 4) * 16);
    uint32_t aB[4];
#pragma unroll
    for (int p = 0; p < 4; p++)
        aB[p] = sb + YSB + (uint32_t)((lane & 15) * 272 + (wn + p * 16 + (lane >> 4) * 8) * 2);

    float acc[4][8][4];
#pragma unroll
    for (int i = 0; i < 4; i++)
#pragma unroll
        for (int j = 0; j < 8; j++)
#pragma unroll
            for (int r = 0; r < 4; r++) acc[i][j][r] = 0.0f;

    auto issue = [&](int buf, int k0) {
#pragma unroll
        for (int i = 0; i < 8; i++) {
            int id = t + i * 128;
            int half = id >> 9, id2 = id & 511, row = id2 >> 2, cs = id2 & 3;
            const __nv_bfloat16* src = (half ? g_wq_l : g_wq_h)
                + (size_t)(m0 + row) * CO + k0 + cs * 8;
            CP_ASYNC(sb + YSA + buf * YSA_BUF + half * YSA_HALF + row * 80 + cs * 16, src);
        }
#pragma unroll
        for (int i = 0; i < 8; i++) {
            int id = t + i * 128;
            int plane = id >> 9, id2 = id & 511, row = id2 >> 4, c = id2 & 15;
            const __nv_bfloat16* src = (plane ? g_fl : g_fh)
                + (size_t)(b * CO + k0 + row) * HW + n0 + c * 8;
            CP_ASYNC(sb + YSB + buf * YSB_BUF + plane * YSB_PL + row * 272 + c * 16, src);
        }
    };

    issue(0, 0); CP_COMMIT();
    const int NI = CO / 32;
    for (int it = 0; it < NI; it++) {
        const int buf = it & 1;
        CP_WAIT0();
        __syncthreads();
        if (it + 1 < NI) { issue(buf ^ 1, (it + 1) * 32); CP_COMMIT(); }

        const uint32_t offA = buf * YSA_BUF, offB = buf * YSB_BUF;
#pragma unroll
        for (int ks = 0; ks < 2; ks++) {
            const uint32_t oA = offA + ks * 32, oB = offB + ks * 4352;
            uint32_t af[4][4], bh[8][2], bl[8][2];
#pragma unroll
            for (int p = 0; p < 4; p++)
                ldm_x4t(bh[2 * p][0], bh[2 * p][1], bh[2 * p + 1][0], bh[2 * p + 1][1],
                        aB[p] + oB);
#pragma unroll
            for (int mt = 0; mt < 4; mt++)
                ldm_x4(af[mt][0], af[mt][1], af[mt][2], af[mt][3], aA[mt] + oA);
#pragma unroll
            for (int mt = 0; mt < 4; mt++)
#pragma unroll
                for (int nt = 0; nt < 8; nt++)
                    mma16816(acc[mt][nt], af[mt][0], af[mt][1], af[mt][2], af[mt][3],
                             bh[nt][0], bh[nt][1]);
#pragma unroll
            for (int p = 0; p < 4; p++)
                ldm_x4t(bl[2 * p][0], bl[2 * p][1], bl[2 * p + 1][0], bl[2 * p + 1][1],
                        aB[p] + oB + YSB_PL);
#pragma unroll
            for (int mt = 0; mt < 4; mt++)
#pragma unroll
                for (int nt = 0; nt < 8; nt++)
                    mma16816(acc[mt][nt], af[mt][0], af[mt][1], af[mt][2], af[mt][3],
                             bl[nt][0], bl[nt][1]);
#pragma unroll
            for (int mt = 0; mt < 4; mt++)
                ldm_x4(af[mt][0], af[mt][1], af[mt][2], af[mt][3], aA[mt] + oA + YSA_HALF);
#pragma unroll
            for (int mt = 0; mt < 4; mt++)
#pragma unroll
                for (int nt = 0; nt < 8; nt++)
                    mma16816(acc[mt][nt], af[mt][0], af[mt][1], af[mt][2], af[mt][3],
                             bh[nt][0], bh[nt][1]);
        }
    }

    // writeback with bias + routing; fused partial vsum for V rows
#pragma unroll
    for (int mt = 0; mt < 4; mt++) {
#pragma unroll
        for (int half = 0; half < 2; half++) {
            int mg = m0 + wm + mt * 16 + g + half * 8;
            if (mg >= 320) continue;
            float bias; float* dst;
            if (mg < 32)      { bias = bq[mg];      dst = g_q + (size_t)(b * CQ + mg) * HW; }
            else if (mg < 64) { bias = bk[mg - 32]; dst = g_k + (size_t)(b * CQ + mg - 32) * HW; }
            else              { bias = bv[mg - 64]; dst = g_v + (size_t)(b * CO + mg - 64) * HW; }
            dst += n0 + wn + 2 * tg;
            float rsum = 0.0f;
#pragma unroll
            for (int nt = 0; nt < 8; nt++) {
                float v0 = acc[mt][nt][2 * half] + bias;
                float v1 = acc[mt][nt][2 * half + 1] + bias;
                *(float2*)(dst + nt * 8) = make_float2(v0, v1);
                rsum += v0 + v1;
            }
            if (mg >= 64) {
                rsum += __shfl_xor_sync(0xffffffffu, rsum, 1);
                rsum += __shfl_xor_sync(0xffffffffu, rsum, 2);
                if (tg == 0) atomicAdd(&g_vsum[b * CO + mg - 64], rsum);
            }
        }
    }
}

// ---------------------------------------------------------------------------
// L2-normalize Q and K over channels per position, accumulate Ksum
__global__ __launch_bounds__(256) void normalize_qk() {
    const int b = blockIdx.y;
    const int n = blockIdx.x * 256 + threadIdx.x;
    const int lane = threadIdx.x & 31;

    {
        float q[CQ];
        float s = 0.0f;
#pragma unroll
        for (int c = 0; c < CQ; c++) {
            q[c] = g_q[(size_t)(b * CQ + c) * HW + n];
            s += q[c] * q[c];
        }
        float sc = 1.0f / fmaxf(sqrtf(s), 1e-6f);
#pragma unroll
        for (int c = 0; c < CQ; c++)
            g_q[(size_t)(b * CQ + c) * HW + n] = q[c] * sc;
    }
    {
        float k[CQ];
        float s = 0.0f;
#pragma unroll
        for (int c = 0; c < CQ; c++) {
            k[c] = g_k[(size_t)(b * CQ + c) * HW + n];
            s += k[c] * k[c];
        }
        float sc = 1.0f / fmaxf(sqrtf(s), 1e-6f);
#pragma unroll
        for (int c = 0; c < CQ; c++) {
            float v = k[c] * sc;
            g_k[(size_t)(b * CQ + c) * HW + n] = v;
            float r = v;
#pragma unroll
            for (int off = 16; off > 0; off >>= 1)
                r += __shfl_down_sync(0xffffffffu, r, off);
            if (lane == 0) atomicAdd(&g_ksum[b * CQ + c], r);
        }
    }
}

// ---------------------------------------------------------------------------
// matrix[b,q,c] = sum_n Kn[b,q,n] * V[b,c,n]  (split-K over n, atomic reduce)
__global__ __launch_bounds__(256) void matrix_kernel() {
    const int b   = blockIdx.z;
    const int c0  = blockIdx.y * 64;
    const int nb0 = blockIdx.x * 512;

    __shared__ float sK[CQ][65];
    __shared__ float sV[64][65];

    const int t  = threadIdx.x;
    const int c  = t & 63;
    const int qg = t >> 6;

    float acc[8];
#pragma unroll
    for (int i = 0; i < 8; i++) acc[i] = 0.0f;

    for (int nb = nb0; nb < nb0 + 512; nb += 64) {
#pragma unroll
        for (int i = 0; i < 8; i++) {
            int idx = t + i * 256;
            int q = idx >> 6, j = idx & 63;
            sK[q][j] = g_k[(size_t)(b * CQ + q) * HW + nb + j];
        }
#pragma unroll
        for (int i = 0; i < 16; i++) {
            int idx = t + i * 256;
            int cc = idx >> 6, j = idx & 63;
            sV[cc][j] = g_v[(size_t)(b * CO + c0 + cc) * HW + nb + j];
        }
        __syncthreads();
#pragma unroll 8
        for (int j = 0; j < 64; j++) {
            float vv = sV[c][j];
#pragma unroll
            for (int i = 0; i < 8; i++)
                acc[i] += sK[qg * 8 + i][j] * vv;
        }
        __syncthreads();
    }
#pragma unroll
    for (int i = 0; i < 8; i++)
        atomicAdd(&g_matrix[(size_t)(b * CQ + qg * 8 + i) * CO + c0 + c], acc[i]);
}

// ---------------------------------------------------------------------------
// Final: out = nan_to_num(gamma * (Vsum + Qn^T matrix) * tailor) + feat
// feat = relu(bn(g_x)) computed inline.
__global__ __launch_bounds__(128) void final_kernel(
    const float* __restrict__ gamma_p,
    const float* __restrict__ bn_gamma, const float* __restrict__ bn_beta,
    float* __restrict__ out)
{
    const int b = blockIdx.y;
    const int n = blockIdx.x * 128 + threadIdx.x;
    const int tid = threadIdx.x;

    __shared__ float sM[CQ][CO];   // 32 KB
    __shared__ float sVs[CO];
    __shared__ float sKs[CQ];
    __shared__ float sScale[CO];
    __shared__ float sShift[CO];

#pragma unroll
    for (int i = 0; i < 64; i++) {
        int idx = tid + i * 128;
        ((float*)sM)[idx] = g_matrix[(size_t)b * CQ * CO + idx];
    }
#pragma unroll
    for (int r = 0; r < 2; r++) {
        int c = tid + r * 128;
        sVs[c] = g_vsum[b * CO + c];
        float scale = g_invstd[c] * bn_gamma[c];
        sScale[c] = scale;
        sShift[c] = bn_beta[c] - g_mean[c] * scale;
    }
    if (tid < CQ) sKs[tid] = g_ksum[b * CQ + tid];
    __syncthreads();

    float qn[CQ];
    float e = 0.0f;
#pragma unroll
    for (int q = 0; q < CQ; q++) {
        qn[q] = g_q[(size_t)(b * CQ + q) * HW + n];
        e += qn[q] * sKs[q];
    }
    const float tailor = 1.0f / fmaxf(NPOS + e, 1e-6f);
    const float gm = *gamma_p;

    for (int c0 = 0; c0 < CO; c0 += 4) {
        float4 a = *(const float4*)&sVs[c0];
#pragma unroll
        for (int q = 0; q < CQ; q++) {
            float4 m4 = *(const float4*)&sM[q][c0];
            a.x += qn[q] * m4.x;
            a.y += qn[q] * m4.y;
            a.z += qn[q] * m4.z;
            a.w += qn[q] * m4.w;
        }
        float r0 = fixnum(gm * a.x * tailor);
        float r1 = fixnum(gm * a.y * tailor);
        float r2 = fixnum(gm * a.z * tailor);
        float r3 = fixnum(gm * a.w * tailor);
        size_t base = (size_t)(b * CO + c0) * HW + n;
        float f0 = fmaxf(g_x[base + 0 * HW] * sScale[c0 + 0] + sShift[c0 + 0], 0.0f);
        float f1 = fmaxf(g_x[base + 1 * HW] * sScale[c0 + 1] + sShift[c0 + 1], 0.0f);
        float f2 = fmaxf(g_x[base + 2 * HW] * sScale[c0 + 2] + sShift[c0 + 2], 0.0f);
        float f3 = fmaxf(g_x[base + 3 * HW] * sScale[c0 + 3] + sShift[c0 + 3], 0.0f);
        out[base + 0 * HW] = r0 + f0;
        out[base + 1 * HW] = r1 + f1;
        out[base + 2 * HW] = r2 + f2;
        out[base + 3 * HW] = r3 + f3;
    }
}

// ---------------------------------------------------------------------------
extern "C" void kernel_launch(void* const* d_in, const int* in_sizes, int n_in,
                              void* d_out, int out_size)
{
    const float* s5 = (const float*)d_in[0];
    const float* s4 = (const float*)d_in[1];
    const float* s3 = (const float*)d_in[2];
    const float* s2 = (const float*)d_in[3];
    const float* w_conv   = (const float*)d_in[4];
    const float* bn_gamma = (const float*)d_in[5];
    const float* bn_beta  = (const float*)d_in[6];
    const float* wq = (const float*)d_in[7];
    const float* bq = (const float*)d_in[8];
    const float* wk = (const float*)d_in[9];
    const float* bk = (const float*)d_in[10];
    const float* wv = (const float*)d_in[11];
    const float* bv = (const float*)d_in[12];
    const float* gamma = (const float*)d_in[13];
    float* out = (float*)d_out;

    static int attr_done = 0;
    if (!attr_done) {
        cudaFuncSetAttribute(conv_gemm_mma, cudaFuncAttributeMaxDynamicSharedMemorySize, YTOT);
        cudaFuncSetAttribute(qkv_gemm_mma,  cudaFuncAttributeMaxDynamicSharedMemorySize, YTOT);
        attr_done = 1;
    }

    zero_kernel<<<64, 256>>>();
    convert_weights<<<1408, 256>>>(w_conv, wq, wk, wv);
    convert_inputs<<<65536, 256>>>(s5, s4, s3, s2);
    conv_gemm_mma<<<dim3(HW / 128, 2, BB), 128, YTOT>>>();
    bn_stats<<<CO, 512>>>();
    convert_feat<<<16384, 256>>>(bn_gamma, bn_beta);
    qkv_gemm_mma<<<dim3(HW / 128, 3, BB), 128, YTOT>>>(bq, bk, bv);
    normalize_qk<<<dim3(HW / 256, BB), 256>>>();
    matrix_kernel<<<dim3(32, CO / 64, BB), 256>>>();
    final_kernel<<<dim3(HW / 128, BB), 128>>>(gamma, bn_gamma, bn_beta, out);
}

// round 15
// speedup vs baseline: 1.0948x; 1.0948x over previous
#include <cuda_runtime.h>
#include <cuda_fp16.h>
#include <math.h>
#include <stdint.h>

// Problem constants
#define BB   4
#define CINE 256
#define CIN  1024
#define CO   256
#define HW   16384        // H*W = 128*128
#define CQ   32
#define NPOS 16384.0f

// GEMM smem layout (bytes). A: [buf][128 rows][80B], B: [buf][32 k-rows][272B]
#define ZSA      0
#define ZSA_BUF  10240
#define ZSB      20480
#define ZSB_BUF  8704
#define ZTOT     37888

// Scratch (device globals -- no runtime allocation allowed)
__device__ float g_x[(size_t)BB * CO * HW];   // raw conv output (pre-BN)
__device__ float g_v[(size_t)BB * CO * HW];   // V
__device__ float g_q[BB * CQ * HW];           // Q then Qn
__device__ float g_k[BB * CQ * HW];           // K then Kn
__device__ float g_mean[CO];
__device__ float g_invstd[CO];
__device__ float g_ksum[BB * CQ];
__device__ float g_vsum[BB * CO];
__device__ float g_matrix[BB * CQ * CO];
// fp16 single-plane operands
__device__ __half g_wc[CO * CIN];
__device__ __half g_wq[384 * CO];                    // rows 320..383 zero
__device__ __half g_bf[(size_t)BB * CIN * HW];       // converted inputs [b][c][n]
__device__ __half g_ff[(size_t)BB * CO * HW];        // converted feat

__device__ __forceinline__ float fixnum(float r) {
    if (isnan(r)) return 0.0f;
    if (isinf(r)) return r > 0.0f ? 1.0f : -1.0f;
    return r;
}

__device__ __forceinline__ uint32_t smem_u32(const void* p) {
    uint32_t a;
    asm("{ .reg .u64 t; cvta.to.shared.u64 t, %1; cvt.u32.u64 %0, t; }"
        : "=r"(a) : "l"(p));
    return a;
}

#define CP_ASYNC(dst, src) \
    asm volatile("cp.async.cg.shared.global [%0], [%1], 16;" :: "r"(dst), "l"(src))
#define CP_COMMIT() asm volatile("cp.async.commit_group;" ::: "memory")
#define CP_WAIT0()  asm volatile("cp.async.wait_group 0;" ::: "memory")

__device__ __forceinline__ void ldm_x4(uint32_t& r0, uint32_t& r1,
                                       uint32_t& r2, uint32_t& r3, uint32_t addr) {
    asm volatile("ldmatrix.sync.aligned.m8n8.x4.shared.b16 {%0,%1,%2,%3}, [%4];"
                 : "=r"(r0), "=r"(r1), "=r"(r2), "=r"(r3) : "r"(addr));
}
__device__ __forceinline__ void ldm_x4t(uint32_t& r0, uint32_t& r1,
                                        uint32_t& r2, uint32_t& r3, uint32_t addr) {
    asm volatile("ldmatrix.sync.aligned.m8n8.x4.trans.shared.b16 {%0,%1,%2,%3}, [%4];"
                 : "=r"(r0), "=r"(r1), "=r"(r2), "=r"(r3) : "r"(addr));
}

// pack two floats to half2 (x -> low 16 bits)
__device__ __forceinline__ uint32_t pack_h2(float x, float y) {
    __half2 h = __floats2half2_rn(x, y);
    return *reinterpret_cast<uint32_t*>(&h);
}

// m16n8k16 row.col fp16 MMA, f32 accumulate in-place
__device__ __forceinline__ void mma16816(float* c,
    uint32_t a0, uint32_t a1, uint32_t a2, uint32_t a3,
    uint32_t b0, uint32_t b1)
{
    asm volatile(
        "mma.sync.aligned.m16n8k16.row.col.f32.f16.f16.f32 "
        "{%0,%1,%2,%3}, {%4,%5,%6,%7}, {%8,%9}, {%0,%1,%2,%3};"
        : "+f"(c[0]), "+f"(c[1]), "+f"(c[2]), "+f"(c[3])
        : "r"(a0), "r"(a1), "r"(a2), "r"(a3), "r"(b0), "r"(b1));
}

// ---------------------------------------------------------------------------
__global__ void zero_kernel() {
    int tid = blockIdx.x * blockDim.x + threadIdx.x;
    int total = BB * CQ + BB * CQ * CO + BB * CO;
    for (int i = tid; i < total; i += gridDim.x * blockDim.x) {
        if (i < BB * CQ) g_ksum[i] = 0.0f;
        else if (i < BB * CQ + BB * CQ * CO) g_matrix[i - BB * CQ] = 0.0f;
        else g_vsum[i - BB * CQ - BB * CQ * CO] = 0.0f;
    }
}

// ---------------------------------------------------------------------------
// Convert weights to fp16.
__global__ __launch_bounds__(256) void convert_weights(
    const float* __restrict__ w,
    const float* __restrict__ wq, const float* __restrict__ wk,
    const float* __restrict__ wv)
{
    int idx = blockIdx.x * 256 + threadIdx.x;
    if (idx < CO * CIN) {
        g_wc[idx] = __float2half_rn(w[idx]);
    } else {
        int j = idx - CO * CIN;
        if (j < 384 * CO) {
            int row = j >> 8, k = j & 255;
            float f = (row < 32)  ? wq[row * CO + k]
                    : (row < 64)  ? wk[(row - 32) * CO + k]
                    : (row < 320) ? wv[(row - 64) * CO + k] : 0.0f;
            g_wq[j] = __float2half_rn(f);
        }
    }
}

// ---------------------------------------------------------------------------
// Convert concatenated inputs to fp16 (elementwise, BW-bound).
__global__ __launch_bounds__(256) void convert_inputs(
    const float* __restrict__ s5, const float* __restrict__ s4,
    const float* __restrict__ s3, const float* __restrict__ s2)
{
    size_t idx4 = (size_t)blockIdx.x * 256 + threadIdx.x;   // float4 index
    int n4 = (int)(idx4 & 4095);                            // HW/4 = 4096
    size_t rest = idx4 >> 12;
    int c = (int)(rest & (CIN - 1));
    int b = (int)(rest >> 10);
    const float* src = (c < 512) ? (c < 256 ? s5 : s4) : (c < 768 ? s3 : s2);
    float4 v = ((const float4*)src)[(size_t)(b * CINE + (c & 255)) * 4096 + n4];
    ((uint2*)g_bf)[idx4] = make_uint2(pack_h2(v.x, v.y), pack_h2(v.z, v.w));
}

// ---------------------------------------------------------------------------
// BN + ReLU + convert feat to fp16.
__global__ __launch_bounds__(256) void convert_feat(
    const float* __restrict__ bn_gamma, const float* __restrict__ bn_beta)
{
    size_t idx4 = (size_t)blockIdx.x * 256 + threadIdx.x;
    int c = (int)((idx4 >> 12) & (CO - 1));
    float sc = g_invstd[c] * bn_gamma[c];
    float sf = bn_beta[c] - g_mean[c] * sc;
    float4 v = ((const float4*)g_x)[idx4];
    v.x = fmaxf(v.x * sc + sf, 0.0f);
    v.y = fmaxf(v.y * sc + sf, 0.0f);
    v.z = fmaxf(v.z * sc + sf, 0.0f);
    v.w = fmaxf(v.w * sc + sf, 0.0f);
    ((uint2*)g_ff)[idx4] = make_uint2(pack_h2(v.x, v.y), pack_h2(v.z, v.w));
}

// ---------------------------------------------------------------------------
// conv 1x1: g_x[b,m,n] = sum_c w[m,c]*fcat[b,c,n]. CTA 128x128, k-chunk 32,
// 4 warps of 64x64.  Single fp16 pass: loop = cp.async + ldmatrix + mma.
__global__ __launch_bounds__(128, 2) void conv_gemm_mma()
{
    extern __shared__ char smem[];
    const uint32_t sb = smem_u32(smem);

    const int t = threadIdx.x;
    const int wid = t >> 5, lane = t & 31;
    const int g = lane >> 2, tg = lane & 3;
    const int b = blockIdx.z, m0 = blockIdx.y * 128, n0 = blockIdx.x * 128;
    const int wm = (wid & 1) * 64, wn = (wid >> 1) * 64;

    uint32_t aA[4];
#pragma unroll
    for (int mt = 0; mt < 4; mt++)
        aA[mt] = sb + ZSA + (uint32_t)((wm + mt * 16 + (lane & 15)) * 80 + (lane >> 4) * 16);
    uint32_t aB[4];
#pragma unroll
    for (int p = 0; p < 4; p++)
        aB[p] = sb + ZSB + (uint32_t)((lane & 15) * 272 + (wn + p * 16 + (lane >> 4) * 8) * 2);

    float acc[4][8][4];
#pragma unroll
    for (int i = 0; i < 4; i++)
#pragma unroll
        for (int j = 0; j < 8; j++)
#pragma unroll
            for (int r = 0; r < 4; r++) acc[i][j][r] = 0.0f;

    auto issue = [&](int buf, int k0) {
#pragma unroll
        for (int i = 0; i < 4; i++) {        // A: 512 chunks [row 128][4x16B]
            int id = t + i * 128;
            int row = id >> 2, cs = id & 3;
            const __half* src = g_wc + (size_t)(m0 + row) * CIN + k0 + cs * 8;
            CP_ASYNC(sb + ZSA + buf * ZSA_BUF + row * 80 + cs * 16, src);
        }
#pragma unroll
        for (int i = 0; i < 4; i++) {        // B: 512 chunks [k 32][16x16B]
            int id = t + i * 128;
            int row = id >> 4, c = id & 15;
            const __half* src = g_bf + (size_t)(b * CIN + k0 + row) * HW + n0 + c * 8;
            CP_ASYNC(sb + ZSB + buf * ZSB_BUF + row * 272 + c * 16, src);
        }
    };

    issue(0, 0); CP_COMMIT();
    const int NI = CIN / 32;
    for (int it = 0; it < NI; it++) {
        const int buf = it & 1;
        CP_WAIT0();
        __syncthreads();
        if (it + 1 < NI) { issue(buf ^ 1, (it + 1) * 32); CP_COMMIT(); }

        const uint32_t offA = buf * ZSA_BUF, offB = buf * ZSB_BUF;
#pragma unroll
        for (int ks = 0; ks < 2; ks++) {
            const uint32_t oA = offA + ks * 32, oB = offB + ks * 4352;
            uint32_t af[4][4], bf[8][2];
#pragma unroll
            for (int p = 0; p < 4; p++)
                ldm_x4t(bf[2 * p][0], bf[2 * p][1], bf[2 * p + 1][0], bf[2 * p + 1][1],
                        aB[p] + oB);
#pragma unroll
            for (int mt = 0; mt < 4; mt++)
                ldm_x4(af[mt][0], af[mt][1], af[mt][2], af[mt][3], aA[mt] + oA);
#pragma unroll
            for (int mt = 0; mt < 4; mt++)
#pragma unroll
                for (int nt = 0; nt < 8; nt++)
                    mma16816(acc[mt][nt], af[mt][0], af[mt][1], af[mt][2], af[mt][3],
                             bf[nt][0], bf[nt][1]);
        }
    }

    // writeback
#pragma unroll
    for (int mt = 0; mt < 4; mt++) {
        int m = m0 + wm + mt * 16 + g;
        float* base = g_x + (size_t)(b * CO + m) * HW + n0 + wn + 2 * tg;
#pragma unroll
        for (int nt = 0; nt < 8; nt++) {
            float* p = base + nt * 8;
            *(float2*)p = make_float2(acc[mt][nt][0], acc[mt][nt][1]);
            *(float2*)(p + 8 * HW) = make_float2(acc[mt][nt][2], acc[mt][nt][3]);
        }
    }
}

// ---------------------------------------------------------------------------
// BN statistics over raw conv output: one block per channel
__global__ __launch_bounds__(512) void bn_stats() {
    const int co = blockIdx.x;
    const int tid = threadIdx.x;
    float s = 0.0f, ss = 0.0f;
    for (int b = 0; b < BB; b++) {
        const float* p = g_x + (size_t)(b * CO + co) * HW;
        for (int i = tid; i < HW; i += 512) {
            float v = p[i];
            s += v;
            ss += v * v;
        }
    }
    __shared__ float rs[512], rss[512];
    rs[tid] = s; rss[tid] = ss;
    __syncthreads();
    for (int off = 256; off > 0; off >>= 1) {
        if (tid < off) { rs[tid] += rs[tid + off]; rss[tid] += rss[tid + off]; }
        __syncthreads();
    }
    if (tid == 0) {
        const float cnt = (float)(BB * HW);
        float mean = rs[0] / cnt;
        float var  = rss[0] / cnt - mean * mean;
        g_mean[co]   = mean;
        g_invstd[co] = rsqrtf(var + 1e-5f);
    }
}

// ---------------------------------------------------------------------------
// QKV GEMM over fp16 feat. Fused vsum in epilogue.
// rows 0..31 = Q, 32..63 = K, 64..319 = V.
__global__ __launch_bounds__(128, 2) void qkv_gemm_mma(
    const float* __restrict__ bq, const float* __restrict__ bk,
    const float* __restrict__ bv)
{
    extern __shared__ char smem[];
    const uint32_t sb = smem_u32(smem);

    const int t = threadIdx.x;
    const int wid = t >> 5, lane = t & 31;
    const int g = lane >> 2, tg = lane & 3;
    const int b = blockIdx.z, m0 = blockIdx.y * 128, n0 = blockIdx.x * 128;
    const int wm = (wid & 1) * 64, wn = (wid >> 1) * 64;

    uint32_t aA[4];
#pragma unroll
    for (int mt = 0; mt < 4; mt++)
        aA[mt] = sb + ZSA + (uint32_t)((wm + mt * 16 + (lane & 15)) * 80 + (lane >> 4) * 16);
    uint32_t aB[4];
#pragma unroll
    for (int p = 0; p < 4; p++)
        aB[p] = sb + ZSB + (uint32_t)((lane & 15) * 272 + (wn + p * 16 + (lane >> 4) * 8) * 2);

    float acc[4][8][4];
#pragma unroll
    for (int i = 0; i < 4; i++)
#pragma unroll
        for (int j = 0; j < 8; j++)
#pragma unroll
            for (int r = 0; r < 4; r++) acc[i][j][r] = 0.0f;

    auto issue = [&](int buf, int k0) {
#pragma unroll
        for (int i = 0; i < 4; i++) {
            int id = t + i * 128;
            int row = id >> 2, cs = id & 3;
            const __half* src = g_wq + (size_t)(m0 + row) * CO + k0 + cs * 8;
            CP_ASYNC(sb + ZSA + buf * ZSA_BUF + row * 80 + cs * 16, src);
        }
#pragma unroll
        for (int i = 0; i < 4; i++) {
            int id = t + i * 128;
            int row = id >> 4, c = id & 15;
            const __half* src = g_ff + (size_t)(b * CO + k0 + row) * HW + n0 + c * 8;
            CP_ASYNC(sb + ZSB + buf * ZSB_BUF + row * 272 + c * 16, src);
        }
    };

    issue(0, 0); CP_COMMIT();
    const int NI = CO / 32;
    for (int it = 0; it < NI; it++) {
        const int buf = it & 1;
        CP_WAIT0();
        __syncthreads();
        if (it + 1 < NI) { issue(buf ^ 1, (it + 1) * 32); CP_COMMIT(); }

        const uint32_t offA = buf * ZSA_BUF, offB = buf * ZSB_BUF;
#pragma unroll
        for (int ks = 0; ks < 2; ks++) {
            const uint32_t oA = offA + ks * 32, oB = offB + ks * 4352;
            uint32_t af[4][4], bf[8][2];
#pragma unroll
            for (int p = 0; p < 4; p++)
                ldm_x4t(bf[2 * p][0], bf[2 * p][1], bf[2 * p + 1][0], bf[2 * p + 1][1],
                        aB[p] + oB);
#pragma unroll
            for (int mt = 0; mt < 4; mt++)
                ldm_x4(af[mt][0], af[mt][1], af[mt][2], af[mt][3], aA[mt] + oA);
#pragma unroll
            for (int mt = 0; mt < 4; mt++)
#pragma unroll
                for (int nt = 0; nt < 8; nt++)
                    mma16816(acc[mt][nt], af[mt][0], af[mt][1], af[mt][2], af[mt][3],
                             bf[nt][0], bf[nt][1]);
        }
    }

    // writeback with bias + routing; fused partial vsum for V rows
#pragma unroll
    for (int mt = 0; mt < 4; mt++) {
#pragma unroll
        for (int half = 0; half < 2; half++) {
            int mg = m0 + wm + mt * 16 + g + half * 8;
            if (mg >= 320) continue;
            float bias; float* dst;
            if (mg < 32)      { bias = bq[mg];      dst = g_q + (size_t)(b * CQ + mg) * HW; }
            else if (mg < 64) { bias = bk[mg - 32]; dst = g_k + (size_t)(b * CQ + mg - 32) * HW; }
            else              { bias = bv[mg - 64]; dst = g_v + (size_t)(b * CO + mg - 64) * HW; }
            dst += n0 + wn + 2 * tg;
            float rsum = 0.0f;
#pragma unroll
            for (int nt = 0; nt < 8; nt++) {
                float v0 = acc[mt][nt][2 * half] + bias;
                float v1 = acc[mt][nt][2 * half + 1] + bias;
                *(float2*)(dst + nt * 8) = make_float2(v0, v1);
                rsum += v0 + v1;
            }
            if (mg >= 64) {
                rsum += __shfl_xor_sync(0xffffffffu, rsum, 1);
                rsum += __shfl_xor_sync(0xffffffffu, rsum, 2);
                if (tg == 0) atomicAdd(&g_vsum[b * CO + mg - 64], rsum);
            }
        }
    }
}

// ---------------------------------------------------------------------------
// L2-normalize Q and K over channels per position, accumulate Ksum
__global__ __launch_bounds__(256) void normalize_qk() {
    const int b = blockIdx.y;
    const int n = blockIdx.x * 256 + threadIdx.x;
    const int lane = threadIdx.x & 31;

    {
        float q[CQ];
        float s = 0.0f;
#pragma unroll
        for (int c = 0; c < CQ; c++) {
            q[c] = g_q[(size_t)(b * CQ + c) * HW + n];
            s += q[c] * q[c];
        }
        float sc = 1.0f / fmaxf(sqrtf(s), 1e-6f);
#pragma unroll
        for (int c = 0; c < CQ; c++)
            g_q[(size_t)(b * CQ + c) * HW + n] = q[c] * sc;
    }
    {
        float k[CQ];
        float s = 0.0f;
#pragma unroll
        for (int c = 0; c < CQ; c++) {
            k[c] = g_k[(size_t)(b * CQ + c) * HW + n];
            s += k[c] * k[c];
        }
        float sc = 1.0f / fmaxf(sqrtf(s), 1e-6f);
#pragma unroll
        for (int c = 0; c < CQ; c++) {
            float v = k[c] * sc;
            g_k[(size_t)(b * CQ + c) * HW + n] = v;
            float r = v;
#pragma unroll
            for (int off = 16; off > 0; off >>= 1)
                r += __shfl_down_sync(0xffffffffu, r, off);
            if (lane == 0) atomicAdd(&g_ksum[b * CQ + c], r);
        }
    }
}

// ---------------------------------------------------------------------------
// matrix[b,q,c] = sum_n Kn[b,q,n] * V[b,c,n]  (split-K over n, atomic reduce)
__global__ __launch_bounds__(256) void matrix_kernel() {
    const int b   = blockIdx.z;
    const int c0  = blockIdx.y * 64;
    const int nb0 = blockIdx.x * 512;

    __shared__ float sK[CQ][65];
    __shared__ float sV[64][65];

    const int t  = threadIdx.x;
    const int c  = t & 63;
    const int qg = t >> 6;

    float acc[8];
#pragma unroll
    for (int i = 0; i < 8; i++) acc[i] = 0.0f;

    for (int nb = nb0; nb < nb0 + 512; nb += 64) {
#pragma unroll
        for (int i = 0; i < 8; i++) {
            int idx = t + i * 256;
            int q = idx >> 6, j = idx & 63;
            sK[q][j] = g_k[(size_t)(b * CQ + q) * HW + nb + j];
        }
#pragma unroll
        for (int i = 0; i < 16; i++) {
            int idx = t + i * 256;
            int cc = idx >> 6, j = idx & 63;
            sV[cc][j] = g_v[(size_t)(b * CO + c0 + cc) * HW + nb + j];
        }
        __syncthreads();
#pragma unroll 8
        for (int j = 0; j < 64; j++) {
            float vv = sV[c][j];
#pragma unroll
            for (int i = 0; i < 8; i++)
                acc[i] += sK[qg * 8 + i][j] * vv;
        }
        __syncthreads();
    }
#pragma unroll
    for (int i = 0; i < 8; i++)
        atomicAdd(&g_matrix[(size_t)(b * CQ + qg * 8 + i) * CO + c0 + c], acc[i]);
}

// ---------------------------------------------------------------------------
// Final: out = nan_to_num(gamma * (Vsum + Qn^T matrix) * tailor) + feat
// feat = relu(bn(g_x)) computed inline.
__global__ __launch_bounds__(128) void final_kernel(
    const float* __restrict__ gamma_p,
    const float* __restrict__ bn_gamma, const float* __restrict__ bn_beta,
    float* __restrict__ out)
{
    const int b = blockIdx.y;
    const int n = blockIdx.x * 128 + threadIdx.x;
    const int tid = threadIdx.x;

    __shared__ float sM[CQ][CO];   // 32 KB
    __shared__ float sVs[CO];
    __shared__ float sKs[CQ];
    __shared__ float sScale[CO];
    __shared__ float sShift[CO];

#pragma unroll
    for (int i = 0; i < 64; i++) {
        int idx = tid + i * 128;
        ((float*)sM)[idx] = g_matrix[(size_t)b * CQ * CO + idx];
    }
#pragma unroll
    for (int r = 0; r < 2; r++) {
        int c = tid + r * 128;
        sVs[c] = g_vsum[b * CO + c];
        float scale = g_invstd[c] * bn_gamma[c];
        sScale[c] = scale;
        sShift[c] = bn_beta[c] - g_mean[c] * scale;
    }
    if (tid < CQ) sKs[tid] = g_ksum[b * CQ + tid];
    __syncthreads();

    float qn[CQ];
    float e = 0.0f;
#pragma unroll
    for (int q = 0; q < CQ; q++) {
        qn[q] = g_q[(size_t)(b * CQ + q) * HW + n];
        e += qn[q] * sKs[q];
    }
    const float tailor = 1.0f / fmaxf(NPOS + e, 1e-6f);
    const float gm = *gamma_p;

    for (int c0 = 0; c0 < CO; c0 += 4) {
        float4 a = *(const float4*)&sVs[c0];
#pragma unroll
        for (int q = 0; q < CQ; q++) {
            float4 m4 = *(const float4*)&sM[q][c0];
            a.x += qn[q] * m4.x;
            a.y += qn[q] * m4.y;
            a.z += qn[q] * m4.z;
            a.w += qn[q] * m4.w;
        }
        float r0 = fixnum(gm * a.x * tailor);
        float r1 = fixnum(gm * a.y * tailor);
        float r2 = fixnum(gm * a.z * tailor);
        float r3 = fixnum(gm * a.w * tailor);
        size_t base = (size_t)(b * CO + c0) * HW + n;
        float f0 = fmaxf(g_x[base + 0 * HW] * sScale[c0 + 0] + sShift[c0 + 0], 0.0f);
        float f1 = fmaxf(g_x[base + 1 * HW] * sScale[c0 + 1] + sShift[c0 + 1], 0.0f);
        float f2 = fmaxf(g_x[base + 2 * HW] * sScale[c0 + 2] + sShift[c0 + 2], 0.0f);
        float f3 = fmaxf(g_x[base + 3 * HW] * sScale[c0 + 3] + sShift[c0 + 3], 0.0f);
        out[base + 0 * HW] = r0 + f0;
        out[base + 1 * HW] = r1 + f1;
        out[base + 2 * HW] = r2 + f2;
        out[base + 3 * HW] = r3 + f3;
    }
}

// ---------------------------------------------------------------------------
extern "C" void kernel_launch(void* const* d_in, const int* in_sizes, int n_in,
                              void* d_out, int out_size)
{
    const float* s5 = (const float*)d_in[0];
    const float* s4 = (const float*)d_in[1];
    const float* s3 = (const float*)d_in[2];
    const float* s2 = (const float*)d_in[3];
    const float* w_conv   = (const float*)d_in[4];
    const float* bn_gamma = (const float*)d_in[5];
    const float* bn_beta  = (const float*)d_in[6];
    const float* wq = (const float*)d_in[7];
    const float* bq = (const float*)d_in[8];
    const float* wk = (const float*)d_in[9];
    const float* bk = (const float*)d_in[10];
    const float* wv = (const float*)d_in[11];
    const float* bv = (const float*)d_in[12];
    const float* gamma = (const float*)d_in[13];
    float* out = (float*)d_out;

    static int attr_done = 0;
    if (!attr_done) {
        cudaFuncSetAttribute(conv_gemm_mma, cudaFuncAttributeMaxDynamicSharedMemorySize, ZTOT);
        cudaFuncSetAttribute(qkv_gemm_mma,  cudaFuncAttributeMaxDynamicSharedMemorySize, ZTOT);
        attr_done = 1;
    }

    zero_kernel<<<64, 256>>>();
    convert_weights<<<1408, 256>>>(w_conv, wq, wk, wv);
    convert_inputs<<<65536, 256>>>(s5, s4, s3, s2);
    conv_gemm_mma<<<dim3(HW / 128, 2, BB), 128, ZTOT>>>();
    bn_stats<<<CO, 512>>>();
    convert_feat<<<16384, 256>>>(bn_gamma, bn_beta);
    qkv_gemm_mma<<<dim3(HW / 128, 3, BB), 128, ZTOT>>>(bq, bk, bv);
    normalize_qk<<<dim3(HW / 256, BB), 256>>>();
    matrix_kernel<<<dim3(32, CO / 64, BB), 256>>>();
    final_kernel<<<dim3(HW / 128, BB), 128>>>(gamma, bn_gamma, bn_beta, out);
}

// round 16
// speedup vs baseline: 1.3355x; 1.2198x over previous
#include <cuda_runtime.h>
#include <cuda_fp16.h>
#include <math.h>
#include <stdint.h>

// Problem constants
#define BB   4
#define CINE 256
#define CIN  1024
#define CO   256
#define HW   16384        // H*W = 128*128
#define CQ   32
#define NPOS 16384.0f

// GEMM smem layout (bytes), k-chunk 64.
// A: [buf][128 rows][144B], B: [buf][64 k-rows][272B]
#define WSA      0
#define WSA_BUF  18432
#define WSB      36864
#define WSB_BUF  17408
#define WTOT     71680

// Scratch (device globals -- no runtime allocation allowed)
__device__ float g_x[(size_t)BB * CO * HW];   // raw conv output (pre-BN)
__device__ float g_v[(size_t)BB * CO * HW];   // V
__device__ float g_q[BB * CQ * HW];           // Q then Qn
__device__ float g_k[BB * CQ * HW];           // K then Kn
__device__ float g_mean[CO];
__device__ float g_invstd[CO];
__device__ float g_bnsum[CO], g_bnsumsq[CO];
__device__ float g_ksum[BB * CQ];
__device__ float g_vsum[BB * CO];
__device__ float g_matrix[BB * CQ * CO];
// fp16 single-plane operands
__device__ __half g_wc[CO * CIN];
__device__ __half g_wq[384 * CO];                    // rows 320..383 zero
__device__ __half g_bf[(size_t)BB * CIN * HW];       // converted inputs [b][c][n]
__device__ __half g_ff[(size_t)BB * CO * HW];        // converted feat

__device__ __forceinline__ float fixnum(float r) {
    if (isnan(r)) return 0.0f;
    if (isinf(r)) return r > 0.0f ? 1.0f : -1.0f;
    return r;
}

__device__ __forceinline__ uint32_t smem_u32(const void* p) {
    uint32_t a;
    asm("{ .reg .u64 t; cvta.to.shared.u64 t, %1; cvt.u32.u64 %0, t; }"
        : "=r"(a) : "l"(p));
    return a;
}

#define CP_ASYNC(dst, src) \
    asm volatile("cp.async.cg.shared.global [%0], [%1], 16;" :: "r"(dst), "l"(src))
#define CP_COMMIT() asm volatile("cp.async.commit_group;" ::: "memory")
#define CP_WAIT0()  asm volatile("cp.async.wait_group 0;" ::: "memory")

__device__ __forceinline__ void ldm_x4(uint32_t& r0, uint32_t& r1,
                                       uint32_t& r2, uint32_t& r3, uint32_t addr) {
    asm volatile("ldmatrix.sync.aligned.m8n8.x4.shared.b16 {%0,%1,%2,%3}, [%4];"
                 : "=r"(r0), "=r"(r1), "=r"(r2), "=r"(r3) : "r"(addr));
}
__device__ __forceinline__ void ldm_x4t(uint32_t& r0, uint32_t& r1,
                                        uint32_t& r2, uint32_t& r3, uint32_t addr) {
    asm volatile("ldmatrix.sync.aligned.m8n8.x4.trans.shared.b16 {%0,%1,%2,%3}, [%4];"
                 : "=r"(r0), "=r"(r1), "=r"(r2), "=r"(r3) : "r"(addr));
}

// pack two floats to half2 (x -> low 16 bits)
__device__ __forceinline__ uint32_t pack_h2(float x, float y) {
    __half2 h = __floats2half2_rn(x, y);
    return *reinterpret_cast<uint32_t*>(&h);
}

// m16n8k16 row.col fp16 MMA, f32 accumulate in-place
__device__ __forceinline__ void mma16816(float* c,
    uint32_t a0, uint32_t a1, uint32_t a2, uint32_t a3,
    uint32_t b0, uint32_t b1)
{
    asm volatile(
        "mma.sync.aligned.m16n8k16.row.col.f32.f16.f16.f32 "
        "{%0,%1,%2,%3}, {%4,%5,%6,%7}, {%8,%9}, {%0,%1,%2,%3};"
        : "+f"(c[0]), "+f"(c[1]), "+f"(c[2]), "+f"(c[3])
        : "r"(a0), "r"(a1), "r"(a2), "r"(a3), "r"(b0), "r"(b1));
}

// ---------------------------------------------------------------------------
__global__ void zero_kernel() {
    int tid = blockIdx.x * blockDim.x + threadIdx.x;
    int total = BB * CQ + BB * CQ * CO + BB * CO + 2 * CO;
    for (int i = tid; i < total; i += gridDim.x * blockDim.x) {
        if (i < BB * CQ) g_ksum[i] = 0.0f;
        else if (i < BB * CQ + BB * CQ * CO) g_matrix[i - BB * CQ] = 0.0f;
        else if (i < BB * CQ + BB * CQ * CO + BB * CO)
            g_vsum[i - BB * CQ - BB * CQ * CO] = 0.0f;
        else {
            int j = i - BB * CQ - BB * CQ * CO - BB * CO;
            if (j < CO) g_bnsum[j] = 0.0f;
            else g_bnsumsq[j - CO] = 0.0f;
        }
    }
}

// ---------------------------------------------------------------------------
// Convert weights to fp16.
__global__ __launch_bounds__(256) void convert_weights(
    const float* __restrict__ w,
    const float* __restrict__ wq, const float* __restrict__ wk,
    const float* __restrict__ wv)
{
    int idx = blockIdx.x * 256 + threadIdx.x;
    if (idx < CO * CIN) {
        g_wc[idx] = __float2half_rn(w[idx]);
    } else {
        int j = idx - CO * CIN;
        if (j < 384 * CO) {
            int row = j >> 8, k = j & 255;
            float f = (row < 32)  ? wq[row * CO + k]
                    : (row < 64)  ? wk[(row - 32) * CO + k]
                    : (row < 320) ? wv[(row - 64) * CO + k] : 0.0f;
            g_wq[j] = __float2half_rn(f);
        }
    }
}

// ---------------------------------------------------------------------------
// Convert concatenated inputs to fp16 (elementwise, BW-bound).
__global__ __launch_bounds__(256) void convert_inputs(
    const float* __restrict__ s5, const float* __restrict__ s4,
    const float* __restrict__ s3, const float* __restrict__ s2)
{
    size_t idx4 = (size_t)blockIdx.x * 256 + threadIdx.x;   // float4 index
    int n4 = (int)(idx4 & 4095);                            // HW/4 = 4096
    size_t rest = idx4 >> 12;
    int c = (int)(rest & (CIN - 1));
    int b = (int)(rest >> 10);
    const float* src = (c < 512) ? (c < 256 ? s5 : s4) : (c < 768 ? s3 : s2);
    float4 v = ((const float4*)src)[(size_t)(b * CINE + (c & 255)) * 4096 + n4];
    ((uint2*)g_bf)[idx4] = make_uint2(pack_h2(v.x, v.y), pack_h2(v.z, v.w));
}

// ---------------------------------------------------------------------------
// Finalize BN stats from atomically-accumulated sums.
__global__ void bn_finalize() {
    int c = threadIdx.x;
    const float cnt = (float)(BB * HW);
    float mean = g_bnsum[c] / cnt;
    float var  = g_bnsumsq[c] / cnt - mean * mean;
    g_mean[c]   = mean;
    g_invstd[c] = rsqrtf(var + 1e-5f);
}

// ---------------------------------------------------------------------------
// BN + ReLU + convert feat to fp16.
__global__ __launch_bounds__(256) void convert_feat(
    const float* __restrict__ bn_gamma, const float* __restrict__ bn_beta)
{
    size_t idx4 = (size_t)blockIdx.x * 256 + threadIdx.x;
    int c = (int)((idx4 >> 12) & (CO - 1));
    float sc = g_invstd[c] * bn_gamma[c];
    float sf = bn_beta[c] - g_mean[c] * sc;
    float4 v = ((const float4*)g_x)[idx4];
    v.x = fmaxf(v.x * sc + sf, 0.0f);
    v.y = fmaxf(v.y * sc + sf, 0.0f);
    v.z = fmaxf(v.z * sc + sf, 0.0f);
    v.w = fmaxf(v.w * sc + sf, 0.0f);
    ((uint2*)g_ff)[idx4] = make_uint2(pack_h2(v.x, v.y), pack_h2(v.z, v.w));
}

// ---------------------------------------------------------------------------
// conv 1x1: g_x[b,m,n] = sum_c w[m,c]*fcat[b,c,n]. CTA 128x128, k-chunk 64,
// 4 warps of 64x64. BN partial sums fused into epilogue.
__global__ __launch_bounds__(128, 2) void conv_gemm_mma()
{
    extern __shared__ char smem[];
    const uint32_t sb = smem_u32(smem);

    const int t = threadIdx.x;
    const int wid = t >> 5, lane = t & 31;
    const int g = lane >> 2, tg = lane & 3;
    const int b = blockIdx.z, m0 = blockIdx.y * 128, n0 = blockIdx.x * 128;
    const int wm = (wid & 1) * 64, wn = (wid >> 1) * 64;

    uint32_t aA[4];
#pragma unroll
    for (int mt = 0; mt < 4; mt++)
        aA[mt] = sb + WSA + (uint32_t)((wm + mt * 16 + (lane & 15)) * 144 + (lane >> 4) * 16);
    uint32_t aB[4];
#pragma unroll
    for (int p = 0; p < 4; p++)
        aB[p] = sb + WSB + (uint32_t)((lane & 15) * 272 + (wn + p * 16 + (lane >> 4) * 8) * 2);

    float acc[4][8][4];
#pragma unroll
    for (int i = 0; i < 4; i++)
#pragma unroll
        for (int j = 0; j < 8; j++)
#pragma unroll
            for (int r = 0; r < 4; r++) acc[i][j][r] = 0.0f;

    auto issue = [&](int buf, int k0) {
#pragma unroll
        for (int i = 0; i < 8; i++) {        // A: 1024 chunks [row 128][8x16B]
            int id = t + i * 128;
            int row = id >> 3, cs = id & 7;
            const __half* src = g_wc + (size_t)(m0 + row) * CIN + k0 + cs * 8;
            CP_ASYNC(sb + WSA + buf * WSA_BUF + row * 144 + cs * 16, src);
        }
#pragma unroll
        for (int i = 0; i < 8; i++) {        // B: 1024 chunks [k 64][16x16B]
            int id = t + i * 128;
            int row = id >> 4, c = id & 15;
            const __half* src = g_bf + (size_t)(b * CIN + k0 + row) * HW + n0 + c * 8;
            CP_ASYNC(sb + WSB + buf * WSB_BUF + row * 272 + c * 16, src);
        }
    };

    issue(0, 0); CP_COMMIT();
    const int NI = CIN / 64;
    for (int it = 0; it < NI; it++) {
        const int buf = it & 1;
        CP_WAIT0();
        __syncthreads();
        if (it + 1 < NI) { issue(buf ^ 1, (it + 1) * 64); CP_COMMIT(); }

        const uint32_t offA = buf * WSA_BUF, offB = buf * WSB_BUF;
#pragma unroll
        for (int ks = 0; ks < 4; ks++) {
            const uint32_t oA = offA + ks * 32, oB = offB + ks * 4352;
            uint32_t af[4][4], bf[8][2];
#pragma unroll
            for (int p = 0; p < 4; p++)
                ldm_x4t(bf[2 * p][0], bf[2 * p][1], bf[2 * p + 1][0], bf[2 * p + 1][1],
                        aB[p] + oB);
#pragma unroll
            for (int mt = 0; mt < 4; mt++)
                ldm_x4(af[mt][0], af[mt][1], af[mt][2], af[mt][3], aA[mt] + oA);
#pragma unroll
            for (int mt = 0; mt < 4; mt++)
#pragma unroll
                for (int nt = 0; nt < 8; nt++)
                    mma16816(acc[mt][nt], af[mt][0], af[mt][1], af[mt][2], af[mt][3],
                             bf[nt][0], bf[nt][1]);
        }
    }

    // writeback + fused BN partial sums (per-channel sum / sumsq)
#pragma unroll
    for (int mt = 0; mt < 4; mt++) {
#pragma unroll
        for (int half = 0; half < 2; half++) {
            int m = m0 + wm + mt * 16 + g + half * 8;
            float* dst = g_x + (size_t)(b * CO + m) * HW + n0 + wn + 2 * tg;
            float s1 = 0.0f, s2 = 0.0f;
#pragma unroll
            for (int nt = 0; nt < 8; nt++) {
                float v0 = acc[mt][nt][2 * half];
                float v1 = acc[mt][nt][2 * half + 1];
                *(float2*)(dst + nt * 8) = make_float2(v0, v1);
                s1 += v0 + v1;
                s2 += v0 * v0 + v1 * v1;
            }
            s1 += __shfl_xor_sync(0xffffffffu, s1, 1);
            s1 += __shfl_xor_sync(0xffffffffu, s1, 2);
            s2 += __shfl_xor_sync(0xffffffffu, s2, 1);
            s2 += __shfl_xor_sync(0xffffffffu, s2, 2);
            if (tg == 0) {
                atomicAdd(&g_bnsum[m], s1);
                atomicAdd(&g_bnsumsq[m], s2);
            }
        }
    }
}

// ---------------------------------------------------------------------------
// QKV GEMM over fp16 feat, k-chunk 64. Fused vsum in epilogue.
// rows 0..31 = Q, 32..63 = K, 64..319 = V.
__global__ __launch_bounds__(128, 2) void qkv_gemm_mma(
    const float* __restrict__ bq, const float* __restrict__ bk,
    const float* __restrict__ bv)
{
    extern __shared__ char smem[];
    const uint32_t sb = smem_u32(smem);

    const int t = threadIdx.x;
    const int wid = t >> 5, lane = t & 31;
    const int g = lane >> 2, tg = lane & 3;
    const int b = blockIdx.z, m0 = blockIdx.y * 128, n0 = blockIdx.x * 128;
    const int wm = (wid & 1) * 64, wn = (wid >> 1) * 64;

    uint32_t aA[4];
#pragma unroll
    for (int mt = 0; mt < 4; mt++)
        aA[mt] = sb + WSA + (uint32_t)((wm + mt * 16 + (lane & 15)) * 144 + (lane >> 4) * 16);
    uint32_t aB[4];
#pragma unroll
    for (int p = 0; p < 4; p++)
        aB[p] = sb + WSB + (uint32_t)((lane & 15) * 272 + (wn + p * 16 + (lane >> 4) * 8) * 2);

    float acc[4][8][4];
#pragma unroll
    for (int i = 0; i < 4; i++)
#pragma unroll
        for (int j = 0; j < 8; j++)
#pragma unroll
            for (int r = 0; r < 4; r++) acc[i][j][r] = 0.0f;

    auto issue = [&](int buf, int k0) {
#pragma unroll
        for (int i = 0; i < 8; i++) {
            int id = t + i * 128;
            int row = id >> 3, cs = id & 7;
            const __half* src = g_wq + (size_t)(m0 + row) * CO + k0 + cs * 8;
            CP_ASYNC(sb + WSA + buf * WSA_BUF + row * 144 + cs * 16, src);
        }
#pragma unroll
        for (int i = 0; i < 8; i++) {
            int id = t + i * 128;
            int row = id >> 4, c = id & 15;
            const __half* src = g_ff + (size_t)(b * CO + k0 + row) * HW + n0 + c * 8;
            CP_ASYNC(sb + WSB + buf * WSB_BUF + row * 272 + c * 16, src);
        }
    };

    issue(0, 0); CP_COMMIT();
    const int NI = CO / 64;
    for (int it = 0; it < NI; it++) {
        const int buf = it & 1;
        CP_WAIT0();
        __syncthreads();
        if (it + 1 < NI) { issue(buf ^ 1, (it + 1) * 64); CP_COMMIT(); }

        const uint32_t offA = buf * WSA_BUF, offB = buf * WSB_BUF;
#pragma unroll
        for (int ks = 0; ks < 4; ks++) {
            const uint32_t oA = offA + ks * 32, oB = offB + ks * 4352;
            uint32_t af[4][4], bf[8][2];
#pragma unroll
            for (int p = 0; p < 4; p++)
                ldm_x4t(bf[2 * p][0], bf[2 * p][1], bf[2 * p + 1][0], bf[2 * p + 1][1],
                        aB[p] + oB);
#pragma unroll
            for (int mt = 0; mt < 4; mt++)
                ldm_x4(af[mt][0], af[mt][1], af[mt][2], af[mt][3], aA[mt] + oA);
#pragma unroll
            for (int mt = 0; mt < 4; mt++)
#pragma unroll
                for (int nt = 0; nt < 8; nt++)
                    mma16816(acc[mt][nt], af[mt][0], af[mt][1], af[mt][2], af[mt][3],
                             bf[nt][0], bf[nt][1]);
        }
    }

    // writeback with bias + routing; fused partial vsum for V rows
#pragma unroll
    for (int mt = 0; mt < 4; mt++) {
#pragma unroll
        for (int half = 0; half < 2; half++) {
            int mg = m0 + wm + mt * 16 + g + half * 8;
            if (mg >= 320) continue;
            float bias; float* dst;
            if (mg < 32)      { bias = bq[mg];      dst = g_q + (size_t)(b * CQ + mg) * HW; }
            else if (mg < 64) { bias = bk[mg - 32]; dst = g_k + (size_t)(b * CQ + mg - 32) * HW; }
            else              { bias = bv[mg - 64]; dst = g_v + (size_t)(b * CO + mg - 64) * HW; }
            dst += n0 + wn + 2 * tg;
            float rsum = 0.0f;
#pragma unroll
            for (int nt = 0; nt < 8; nt++) {
                float v0 = acc[mt][nt][2 * half] + bias;
                float v1 = acc[mt][nt][2 * half + 1] + bias;
                *(float2*)(dst + nt * 8) = make_float2(v0, v1);
                rsum += v0 + v1;
            }
            if (mg >= 64) {
                rsum += __shfl_xor_sync(0xffffffffu, rsum, 1);
                rsum += __shfl_xor_sync(0xffffffffu, rsum, 2);
                if (tg == 0) atomicAdd(&g_vsum[b * CO + mg - 64], rsum);
            }
        }
    }
}

// ---------------------------------------------------------------------------
// L2-normalize Q and K over channels per position, accumulate Ksum
__global__ __launch_bounds__(256) void normalize_qk() {
    const int b = blockIdx.y;
    const int n = blockIdx.x * 256 + threadIdx.x;
    const int lane = threadIdx.x & 31;

    {
        float q[CQ];
        float s = 0.0f;
#pragma unroll
        for (int c = 0; c < CQ; c++) {
            q[c] = g_q[(size_t)(b * CQ + c) * HW + n];
            s += q[c] * q[c];
        }
        float sc = 1.0f / fmaxf(sqrtf(s), 1e-6f);
#pragma unroll
        for (int c = 0; c < CQ; c++)
            g_q[(size_t)(b * CQ + c) * HW + n] = q[c] * sc;
    }
    {
        float k[CQ];
        float s = 0.0f;
#pragma unroll
        for (int c = 0; c < CQ; c++) {
            k[c] = g_k[(size_t)(b * CQ + c) * HW + n];
            s += k[c] * k[c];
        }
        float sc = 1.0f / fmaxf(sqrtf(s), 1e-6f);
#pragma unroll
        for (int c = 0; c < CQ; c++) {
            float v = k[c] * sc;
            g_k[(size_t)(b * CQ + c) * HW + n] = v;
            float r = v;
#pragma unroll
            for (int off = 16; off > 0; off >>= 1)
                r += __shfl_down_sync(0xffffffffu, r, off);
            if (lane == 0) atomicAdd(&g_ksum[b * CQ + c], r);
        }
    }
}

// ---------------------------------------------------------------------------
// matrix[b,q,c] = sum_n Kn[b,q,n] * V[b,c,n]  (split-K over n, atomic reduce)
__global__ __launch_bounds__(256) void matrix_kernel() {
    const int b   = blockIdx.z;
    const int c0  = blockIdx.y * 64;
    const int nb0 = blockIdx.x * 512;

    __shared__ float sK[CQ][65];
    __shared__ float sV[64][65];

    const int t  = threadIdx.x;
    const int c  = t & 63;
    const int qg = t >> 6;

    float acc[8];
#pragma unroll
    for (int i = 0; i < 8; i++) acc[i] = 0.0f;

    for (int nb = nb0; nb < nb0 + 512; nb += 64) {
#pragma unroll
        for (int i = 0; i < 8; i++) {
            int idx = t + i * 256;
            int q = idx >> 6, j = idx & 63;
            sK[q][j] = g_k[(size_t)(b * CQ + q) * HW + nb + j];
        }
#pragma unroll
        for (int i = 0; i < 16; i++) {
            int idx = t + i * 256;
            int cc = idx >> 6, j = idx & 63;
            sV[cc][j] = g_v[(size_t)(b * CO + c0 + cc) * HW + nb + j];
        }
        __syncthreads();
#pragma unroll 8
        for (int j = 0; j < 64; j++) {
            float vv = sV[c][j];
#pragma unroll
            for (int i = 0; i < 8; i++)
                acc[i] += sK[qg * 8 + i][j] * vv;
        }
        __syncthreads();
    }
#pragma unroll
    for (int i = 0; i < 8; i++)
        atomicAdd(&g_matrix[(size_t)(b * CQ + qg * 8 + i) * CO + c0 + c], acc[i]);
}

// ---------------------------------------------------------------------------
// Final: out = nan_to_num(gamma * (Vsum + Qn^T matrix) * tailor) + feat
// feat read from fp16 plane g_ff.
__global__ __launch_bounds__(128) void final_kernel(
    const float* __restrict__ gamma_p, float* __restrict__ out)
{
    const int b = blockIdx.y;
    const int n = blockIdx.x * 128 + threadIdx.x;
    const int tid = threadIdx.x;

    __shared__ float sM[CQ][CO];   // 32 KB
    __shared__ float sVs[CO];
    __shared__ float sKs[CQ];

#pragma unroll
    for (int i = 0; i < 64; i++) {
        int idx = tid + i * 128;
        ((float*)sM)[idx] = g_matrix[(size_t)b * CQ * CO + idx];
    }
#pragma unroll
    for (int r = 0; r < 2; r++) {
        int c = tid + r * 128;
        sVs[c] = g_vsum[b * CO + c];
    }
    if (tid < CQ) sKs[tid] = g_ksum[b * CQ + tid];
    __syncthreads();

    float qn[CQ];
    float e = 0.0f;
#pragma unroll
    for (int q = 0; q < CQ; q++) {
        qn[q] = g_q[(size_t)(b * CQ + q) * HW + n];
        e += qn[q] * sKs[q];
    }
    const float tailor = 1.0f / fmaxf(NPOS + e, 1e-6f);
    const float gm = *gamma_p;

    for (int c0 = 0; c0 < CO; c0 += 4) {
        float4 a = *(const float4*)&sVs[c0];
#pragma unroll
        for (int q = 0; q < CQ; q++) {
            float4 m4 = *(const float4*)&sM[q][c0];
            a.x += qn[q] * m4.x;
            a.y += qn[q] * m4.y;
            a.z += qn[q] * m4.z;
            a.w += qn[q] * m4.w;
        }
        float r0 = fixnum(gm * a.x * tailor);
        float r1 = fixnum(gm * a.y * tailor);
        float r2 = fixnum(gm * a.z * tailor);
        float r3 = fixnum(gm * a.w * tailor);
        size_t base = (size_t)(b * CO + c0) * HW + n;
        out[base + 0 * HW] = r0 + __half2float(g_ff[base + 0 * HW]);
        out[base + 1 * HW] = r1 + __half2float(g_ff[base + 1 * HW]);
        out[base + 2 * HW] = r2 + __half2float(g_ff[base + 2 * HW]);
        out[base + 3 * HW] = r3 + __half2float(g_ff[base + 3 * HW]);
    }
}

// ---------------------------------------------------------------------------
extern "C" void kernel_launch(void* const* d_in, const int* in_sizes, int n_in,
                              void* d_out, int out_size)
{
    const float* s5 = (const float*)d_in[0];
    const float* s4 = (const float*)d_in[1];
    const float* s3 = (const float*)d_in[2];
    const float* s2 = (const float*)d_in[3];
    const float* w_conv   = (const float*)d_in[4];
    const float* bn_gamma = (const float*)d_in[5];
    const float* bn_beta  = (const float*)d_in[6];
    const float* wq = (const float*)d_in[7];
    const float* bq = (const float*)d_in[8];
    const float* wk = (const float*)d_in[9];
    const float* bk = (const float*)d_in[10];
    const float* wv = (const float*)d_in[11];
    const float* bv = (const float*)d_in[12];
    const float* gamma = (const float*)d_in[13];
    float* out = (float*)d_out;

    static int attr_done = 0;
    if (!attr_done) {
        cudaFuncSetAttribute(conv_gemm_mma, cudaFuncAttributeMaxDynamicSharedMemorySize, WTOT);
        cudaFuncSetAttribute(qkv_gemm_mma,  cudaFuncAttributeMaxDynamicSharedMemorySize, WTOT);
        attr_done = 1;
    }

    zero_kernel<<<64, 256>>>();
    convert_weights<<<1408, 256>>>(w_conv, wq, wk, wv);
    convert_inputs<<<65536, 256>>>(s5, s4, s3, s2);
    conv_gemm_mma<<<dim3(HW / 128, 2, BB), 128, WTOT>>>();
    bn_finalize<<<1, 256>>>();
    convert_feat<<<16384, 256>>>(bn_gamma, bn_beta);
    qkv_gemm_mma<<<dim3(HW / 128, 3, BB), 128, WTOT>>>(bq, bk, bv);
    normalize_qk<<<dim3(HW / 256, BB), 256>>>();
    matrix_kernel<<<dim3(32, CO / 64, BB), 256>>>();
    final_kernel<<<dim3(HW / 128, BB), 128>>>(gamma, out);
}

// round 17
// speedup vs baseline: 1.3957x; 1.0451x over previous
#include <cuda_runtime.h>
#include <cuda_fp16.h>
#include <math.h>
#include <stdint.h>

// Problem constants
#define BB   4
#define CINE 256
#define CIN  1024
#define CO   256
#define HW   16384        // H*W = 128*128
#define CQ   32
#define NPOS 16384.0f

// GEMM smem layout (bytes), k-chunk 64.
// A: [buf][128 rows][144B], B: [buf][64 k-rows][272B]
#define WSA      0
#define WSA_BUF  18432
#define WSB      36864
#define WSB_BUF  17408
#define WTOT     71680

// Scratch (device globals -- no runtime allocation allowed)
__device__ float g_v[(size_t)BB * CO * HW];   // V
__device__ float g_q[BB * CQ * HW];           // Q then Qn
__device__ float g_k[BB * CQ * HW];           // K then Kn
__device__ float g_mean[CO];
__device__ float g_invstd[CO];
__device__ float g_bnsum[CO], g_bnsumsq[CO];
__device__ float g_ksum[BB * CQ];
__device__ float g_vsum[BB * CO];
__device__ float g_matrix[BB * CQ * CO];
// fp16 operands / intermediates
__device__ __half g_wc[CO * CIN];
__device__ __half g_wq[384 * CO];                    // rows 320..383 zero
__device__ __half g_bf[(size_t)BB * CIN * HW];       // converted inputs [b][c][n]
__device__ __half g_xh[(size_t)BB * CO * HW];        // raw conv output (fp16)
__device__ __half g_ff[(size_t)BB * CO * HW];        // feat = relu(bn(x)) fp16

__device__ __forceinline__ float fixnum(float r) {
    if (isnan(r)) return 0.0f;
    if (isinf(r)) return r > 0.0f ? 1.0f : -1.0f;
    return r;
}

__device__ __forceinline__ uint32_t smem_u32(const void* p) {
    uint32_t a;
    asm("{ .reg .u64 t; cvta.to.shared.u64 t, %1; cvt.u32.u64 %0, t; }"
        : "=r"(a) : "l"(p));
    return a;
}

#define CP_ASYNC(dst, src) \
    asm volatile("cp.async.cg.shared.global [%0], [%1], 16;" :: "r"(dst), "l"(src))
#define CP_COMMIT() asm volatile("cp.async.commit_group;" ::: "memory")
#define CP_WAIT0()  asm volatile("cp.async.wait_group 0;" ::: "memory")

__device__ __forceinline__ void ldm_x4(uint32_t& r0, uint32_t& r1,
                                       uint32_t& r2, uint32_t& r3, uint32_t addr) {
    asm volatile("ldmatrix.sync.aligned.m8n8.x4.shared.b16 {%0,%1,%2,%3}, [%4];"
                 : "=r"(r0), "=r"(r1), "=r"(r2), "=r"(r3) : "r"(addr));
}
__device__ __forceinline__ void ldm_x4t(uint32_t& r0, uint32_t& r1,
                                        uint32_t& r2, uint32_t& r3, uint32_t addr) {
    asm volatile("ldmatrix.sync.aligned.m8n8.x4.trans.shared.b16 {%0,%1,%2,%3}, [%4];"
                 : "=r"(r0), "=r"(r1), "=r"(r2), "=r"(r3) : "r"(addr));
}

// pack two floats to half2 (x -> low 16 bits)
__device__ __forceinline__ uint32_t pack_h2(float x, float y) {
    __half2 h = __floats2half2_rn(x, y);
    return *reinterpret_cast<uint32_t*>(&h);
}

// m16n8k16 row.col fp16 MMA, f32 accumulate in-place
__device__ __forceinline__ void mma16816(float* c,
    uint32_t a0, uint32_t a1, uint32_t a2, uint32_t a3,
    uint32_t b0, uint32_t b1)
{
    asm volatile(
        "mma.sync.aligned.m16n8k16.row.col.f32.f16.f16.f32 "
        "{%0,%1,%2,%3}, {%4,%5,%6,%7}, {%8,%9}, {%0,%1,%2,%3};"
        : "+f"(c[0]), "+f"(c[1]), "+f"(c[2]), "+f"(c[3])
        : "r"(a0), "r"(a1), "r"(a2), "r"(a3), "r"(b0), "r"(b1));
}

// ---------------------------------------------------------------------------
__global__ void zero_kernel() {
    int tid = blockIdx.x * blockDim.x + threadIdx.x;
    int total = BB * CQ + BB * CQ * CO + BB * CO + 2 * CO;
    for (int i = tid; i < total; i += gridDim.x * blockDim.x) {
        if (i < BB * CQ) g_ksum[i] = 0.0f;
        else if (i < BB * CQ + BB * CQ * CO) g_matrix[i - BB * CQ] = 0.0f;
        else if (i < BB * CQ + BB * CQ * CO + BB * CO)
            g_vsum[i - BB * CQ - BB * CQ * CO] = 0.0f;
        else {
            int j = i - BB * CQ - BB * CQ * CO - BB * CO;
            if (j < CO) g_bnsum[j] = 0.0f;
            else g_bnsumsq[j - CO] = 0.0f;
        }
    }
}

// ---------------------------------------------------------------------------
// Convert weights to fp16.
__global__ __launch_bounds__(256) void convert_weights(
    const float* __restrict__ w,
    const float* __restrict__ wq, const float* __restrict__ wk,
    const float* __restrict__ wv)
{
    int idx = blockIdx.x * 256 + threadIdx.x;
    if (idx < CO * CIN) {
        g_wc[idx] = __float2half_rn(w[idx]);
    } else {
        int j = idx - CO * CIN;
        if (j < 384 * CO) {
            int row = j >> 8, k = j & 255;
            float f = (row < 32)  ? wq[row * CO + k]
                    : (row < 64)  ? wk[(row - 32) * CO + k]
                    : (row < 320) ? wv[(row - 64) * CO + k] : 0.0f;
            g_wq[j] = __float2half_rn(f);
        }
    }
}

// ---------------------------------------------------------------------------
// Convert concatenated inputs to fp16 (elementwise, BW-bound).
__global__ __launch_bounds__(256) void convert_inputs(
    const float* __restrict__ s5, const float* __restrict__ s4,
    const float* __restrict__ s3, const float* __restrict__ s2)
{
    size_t idx4 = (size_t)blockIdx.x * 256 + threadIdx.x;   // float4 index
    int n4 = (int)(idx4 & 4095);                            // HW/4 = 4096
    size_t rest = idx4 >> 12;
    int c = (int)(rest & (CIN - 1));
    int b = (int)(rest >> 10);
    const float* src = (c < 512) ? (c < 256 ? s5 : s4) : (c < 768 ? s3 : s2);
    float4 v = ((const float4*)src)[(size_t)(b * CINE + (c & 255)) * 4096 + n4];
    ((uint2*)g_bf)[idx4] = make_uint2(pack_h2(v.x, v.y), pack_h2(v.z, v.w));
}

// ---------------------------------------------------------------------------
// Finalize BN stats from atomically-accumulated sums.
__global__ void bn_finalize() {
    int c = threadIdx.x;
    const float cnt = (float)(BB * HW);
    float mean = g_bnsum[c] / cnt;
    float var  = g_bnsumsq[c] / cnt - mean * mean;
    g_mean[c]   = mean;
    g_invstd[c] = rsqrtf(var + 1e-5f);
}

// ---------------------------------------------------------------------------
// BN + ReLU over fp16 raw conv output -> fp16 feat (8 halves per thread).
__global__ __launch_bounds__(256) void convert_feat(
    const float* __restrict__ bn_gamma, const float* __restrict__ bn_beta)
{
    size_t idx8 = (size_t)blockIdx.x * 256 + threadIdx.x;   // 8-half group
    int c = (int)((idx8 >> 11) & (CO - 1));                 // HW/8 = 2048 per (b,c)
    float sc = g_invstd[c] * bn_gamma[c];
    float sf = bn_beta[c] - g_mean[c] * sc;
    uint4 raw = ((const uint4*)g_xh)[idx8];
    uint32_t w[4] = {raw.x, raw.y, raw.z, raw.w};
    uint32_t o[4];
#pragma unroll
    for (int i = 0; i < 4; i++) {
        __half2 h = *reinterpret_cast<__half2*>(&w[i]);
        float2 f = __half22float2(h);
        f.x = fmaxf(f.x * sc + sf, 0.0f);
        f.y = fmaxf(f.y * sc + sf, 0.0f);
        o[i] = pack_h2(f.x, f.y);
    }
    ((uint4*)g_ff)[idx8] = make_uint4(o[0], o[1], o[2], o[3]);
}

// ---------------------------------------------------------------------------
// conv 1x1: x[b,m,n] = sum_c w[m,c]*fcat[b,c,n]. CTA 128x128, k-chunk 64,
// 4 warps of 64x64. Writes fp16 raw output; BN partial sums fused (fp32 accs).
__global__ __launch_bounds__(128, 2) void conv_gemm_mma()
{
    extern __shared__ char smem[];
    const uint32_t sb = smem_u32(smem);

    const int t = threadIdx.x;
    const int wid = t >> 5, lane = t & 31;
    const int g = lane >> 2, tg = lane & 3;
    const int b = blockIdx.z, m0 = blockIdx.y * 128, n0 = blockIdx.x * 128;
    const int wm = (wid & 1) * 64, wn = (wid >> 1) * 64;

    uint32_t aA[4];
#pragma unroll
    for (int mt = 0; mt < 4; mt++)
        aA[mt] = sb + WSA + (uint32_t)((wm + mt * 16 + (lane & 15)) * 144 + (lane >> 4) * 16);
    uint32_t aB[4];
#pragma unroll
    for (int p = 0; p < 4; p++)
        aB[p] = sb + WSB + (uint32_t)((lane & 15) * 272 + (wn + p * 16 + (lane >> 4) * 8) * 2);

    float acc[4][8][4];
#pragma unroll
    for (int i = 0; i < 4; i++)
#pragma unroll
        for (int j = 0; j < 8; j++)
#pragma unroll
            for (int r = 0; r < 4; r++) acc[i][j][r] = 0.0f;

    auto issue = [&](int buf, int k0) {
#pragma unroll
        for (int i = 0; i < 8; i++) {        // A: 1024 chunks [row 128][8x16B]
            int id = t + i * 128;
            int row = id >> 3, cs = id & 7;
            const __half* src = g_wc + (size_t)(m0 + row) * CIN + k0 + cs * 8;
            CP_ASYNC(sb + WSA + buf * WSA_BUF + row * 144 + cs * 16, src);
        }
#pragma unroll
        for (int i = 0; i < 8; i++) {        // B: 1024 chunks [k 64][16x16B]
            int id = t + i * 128;
            int row = id >> 4, c = id & 15;
            const __half* src = g_bf + (size_t)(b * CIN + k0 + row) * HW + n0 + c * 8;
            CP_ASYNC(sb + WSB + buf * WSB_BUF + row * 272 + c * 16, src);
        }
    };

    issue(0, 0); CP_COMMIT();
    const int NI = CIN / 64;
    for (int it = 0; it < NI; it++) {
        const int buf = it & 1;
        CP_WAIT0();
        __syncthreads();
        if (it + 1 < NI) { issue(buf ^ 1, (it + 1) * 64); CP_COMMIT(); }

        const uint32_t offA = buf * WSA_BUF, offB = buf * WSB_BUF;
#pragma unroll
        for (int ks = 0; ks < 4; ks++) {
            const uint32_t oA = offA + ks * 32, oB = offB + ks * 4352;
            uint32_t af[4][4], bf[8][2];
#pragma unroll
            for (int p = 0; p < 4; p++)
                ldm_x4t(bf[2 * p][0], bf[2 * p][1], bf[2 * p + 1][0], bf[2 * p + 1][1],
                        aB[p] + oB);
#pragma unroll
            for (int mt = 0; mt < 4; mt++)
                ldm_x4(af[mt][0], af[mt][1], af[mt][2], af[mt][3], aA[mt] + oA);
#pragma unroll
            for (int mt = 0; mt < 4; mt++)
#pragma unroll
                for (int nt = 0; nt < 8; nt++)
                    mma16816(acc[mt][nt], af[mt][0], af[mt][1], af[mt][2], af[mt][3],
                             bf[nt][0], bf[nt][1]);
        }
    }

    // writeback (fp16) + fused BN partial sums from fp32 accumulators
#pragma unroll
    for (int mt = 0; mt < 4; mt++) {
#pragma unroll
        for (int half = 0; half < 2; half++) {
            int m = m0 + wm + mt * 16 + g + half * 8;
            __half* dst = g_xh + (size_t)(b * CO + m) * HW + n0 + wn + 2 * tg;
            float s1 = 0.0f, s2 = 0.0f;
#pragma unroll
            for (int nt = 0; nt < 8; nt++) {
                float v0 = acc[mt][nt][2 * half];
                float v1 = acc[mt][nt][2 * half + 1];
                *(uint32_t*)(dst + nt * 8) = pack_h2(v0, v1);
                s1 += v0 + v1;
                s2 += v0 * v0 + v1 * v1;
            }
            s1 += __shfl_xor_sync(0xffffffffu, s1, 1);
            s1 += __shfl_xor_sync(0xffffffffu, s1, 2);
            s2 += __shfl_xor_sync(0xffffffffu, s2, 1);
            s2 += __shfl_xor_sync(0xffffffffu, s2, 2);
            if (tg == 0) {
                atomicAdd(&g_bnsum[m], s1);
                atomicAdd(&g_bnsumsq[m], s2);
            }
        }
    }
}

// ---------------------------------------------------------------------------
// QKV GEMM over fp16 feat, k-chunk 64. Fused vsum in epilogue.
// rows 0..31 = Q, 32..63 = K, 64..319 = V.
__global__ __launch_bounds__(128, 2) void qkv_gemm_mma(
    const float* __restrict__ bq, const float* __restrict__ bk,
    const float* __restrict__ bv)
{
    extern __shared__ char smem[];
    const uint32_t sb = smem_u32(smem);

    const int t = threadIdx.x;
    const int wid = t >> 5, lane = t & 31;
    const int g = lane >> 2, tg = lane & 3;
    const int b = blockIdx.z, m0 = blockIdx.y * 128, n0 = blockIdx.x * 128;
    const int wm = (wid & 1) * 64, wn = (wid >> 1) * 64;

    uint32_t aA[4];
#pragma unroll
    for (int mt = 0; mt < 4; mt++)
        aA[mt] = sb + WSA + (uint32_t)((wm + mt * 16 + (lane & 15)) * 144 + (lane >> 4) * 16);
    uint32_t aB[4];
#pragma unroll
    for (int p = 0; p < 4; p++)
        aB[p] = sb + WSB + (uint32_t)((lane & 15) * 272 + (wn + p * 16 + (lane >> 4) * 8) * 2);

    float acc[4][8][4];
#pragma unroll
    for (int i = 0; i < 4; i++)
#pragma unroll
        for (int j = 0; j < 8; j++)
#pragma unroll
            for (int r = 0; r < 4; r++) acc[i][j][r] = 0.0f;

    auto issue = [&](int buf, int k0) {
#pragma unroll
        for (int i = 0; i < 8; i++) {
            int id = t + i * 128;
            int row = id >> 3, cs = id & 7;
            const __half* src = g_wq + (size_t)(m0 + row) * CO + k0 + cs * 8;
            CP_ASYNC(sb + WSA + buf * WSA_BUF + row * 144 + cs * 16, src);
        }
#pragma unroll
        for (int i = 0; i < 8; i++) {
            int id = t + i * 128;
            int row = id >> 4, c = id & 15;
            const __half* src = g_ff + (size_t)(b * CO + k0 + row) * HW + n0 + c * 8;
            CP_ASYNC(sb + WSB + buf * WSB_BUF + row * 272 + c * 16, src);
        }
    };

    issue(0, 0); CP_COMMIT();
    const int NI = CO / 64;
    for (int it = 0; it < NI; it++) {
        const int buf = it & 1;
        CP_WAIT0();
        __syncthreads();
        if (it + 1 < NI) { issue(buf ^ 1, (it + 1) * 64); CP_COMMIT(); }

        const uint32_t offA = buf * WSA_BUF, offB = buf * WSB_BUF;
#pragma unroll
        for (int ks = 0; ks < 4; ks++) {
            const uint32_t oA = offA + ks * 32, oB = offB + ks * 4352;
            uint32_t af[4][4], bf[8][2];
#pragma unroll
            for (int p = 0; p < 4; p++)
                ldm_x4t(bf[2 * p][0], bf[2 * p][1], bf[2 * p + 1][0], bf[2 * p + 1][1],
                        aB[p] + oB);
#pragma unroll
            for (int mt = 0; mt < 4; mt++)
                ldm_x4(af[mt][0], af[mt][1], af[mt][2], af[mt][3], aA[mt] + oA);
#pragma unroll
            for (int mt = 0; mt < 4; mt++)
#pragma unroll
                for (int nt = 0; nt < 8; nt++)
                    mma16816(acc[mt][nt], af[mt][0], af[mt][1], af[mt][2], af[mt][3],
                             bf[nt][0], bf[nt][1]);
        }
    }

    // writeback with bias + routing; fused partial vsum for V rows
#pragma unroll
    for (int mt = 0; mt < 4; mt++) {
#pragma unroll
        for (int half = 0; half < 2; half++) {
            int mg = m0 + wm + mt * 16 + g + half * 8;
            if (mg >= 320) continue;
            float bias; float* dst;
            if (mg < 32)      { bias = bq[mg];      dst = g_q + (size_t)(b * CQ + mg) * HW; }
            else if (mg < 64) { bias = bk[mg - 32]; dst = g_k + (size_t)(b * CQ + mg - 32) * HW; }
            else              { bias = bv[mg - 64]; dst = g_v + (size_t)(b * CO + mg - 64) * HW; }
            dst += n0 + wn + 2 * tg;
            float rsum = 0.0f;
#pragma unroll
            for (int nt = 0; nt < 8; nt++) {
                float v0 = acc[mt][nt][2 * half] + bias;
                float v1 = acc[mt][nt][2 * half + 1] + bias;
                *(float2*)(dst + nt * 8) = make_float2(v0, v1);
                rsum += v0 + v1;
            }
            if (mg >= 64) {
                rsum += __shfl_xor_sync(0xffffffffu, rsum, 1);
                rsum += __shfl_xor_sync(0xffffffffu, rsum, 2);
                if (tg == 0) atomicAdd(&g_vsum[b * CO + mg - 64], rsum);
            }
        }
    }
}

// ---------------------------------------------------------------------------
// L2-normalize Q and K over channels per position, accumulate Ksum
__global__ __launch_bounds__(256) void normalize_qk() {
    const int b = blockIdx.y;
    const int n = blockIdx.x * 256 + threadIdx.x;
    const int lane = threadIdx.x & 31;

    {
        float q[CQ];
        float s = 0.0f;
#pragma unroll
        for (int c = 0; c < CQ; c++) {
            q[c] = g_q[(size_t)(b * CQ + c) * HW + n];
            s += q[c] * q[c];
        }
        float sc = 1.0f / fmaxf(sqrtf(s), 1e-6f);
#pragma unroll
        for (int c = 0; c < CQ; c++)
            g_q[(size_t)(b * CQ + c) * HW + n] = q[c] * sc;
    }
    {
        float k[CQ];
        float s = 0.0f;
#pragma unroll
        for (int c = 0; c < CQ; c++) {
            k[c] = g_k[(size_t)(b * CQ + c) * HW + n];
            s += k[c] * k[c];
        }
        float sc = 1.0f / fmaxf(sqrtf(s), 1e-6f);
#pragma unroll
        for (int c = 0; c < CQ; c++) {
            float v = k[c] * sc;
            g_k[(size_t)(b * CQ + c) * HW + n] = v;
            float r = v;
#pragma unroll
            for (int off = 16; off > 0; off >>= 1)
                r += __shfl_down_sync(0xffffffffu, r, off);
            if (lane == 0) atomicAdd(&g_ksum[b * CQ + c], r);
        }
    }
}

// ---------------------------------------------------------------------------
// matrix[b,q,c] = sum_n Kn[b,q,n] * V[b,c,n]  (split-K over n, atomic reduce)
__global__ __launch_bounds__(256) void matrix_kernel() {
    const int b   = blockIdx.z;
    const int c0  = blockIdx.y * 64;
    const int nb0 = blockIdx.x * 512;

    __shared__ float sK[CQ][65];
    __shared__ float sV[64][65];

    const int t  = threadIdx.x;
    const int c  = t & 63;
    const int qg = t >> 6;

    float acc[8];
#pragma unroll
    for (int i = 0; i < 8; i++) acc[i] = 0.0f;

    for (int nb = nb0; nb < nb0 + 512; nb += 64) {
#pragma unroll
        for (int i = 0; i < 8; i++) {
            int idx = t + i * 256;
            int q = idx >> 6, j = idx & 63;
            sK[q][j] = g_k[(size_t)(b * CQ + q) * HW + nb + j];
        }
#pragma unroll
        for (int i = 0; i < 16; i++) {
            int idx = t + i * 256;
            int cc = idx >> 6, j = idx & 63;
            sV[cc][j] = g_v[(size_t)(b * CO + c0 + cc) * HW + nb + j];
        }
        __syncthreads();
#pragma unroll 8
        for (int j = 0; j < 64; j++) {
            float vv = sV[c][j];
#pragma unroll
            for (int i = 0; i < 8; i++)
                acc[i] += sK[qg * 8 + i][j] * vv;
        }
        __syncthreads();
    }
#pragma unroll
    for (int i = 0; i < 8; i++)
        atomicAdd(&g_matrix[(size_t)(b * CQ + qg * 8 + i) * CO + c0 + c], acc[i]);
}

// ---------------------------------------------------------------------------
// Final: out = nan_to_num(gamma * (Vsum + Qn^T matrix) * tailor) + feat
// feat read from fp16 plane g_ff.
__global__ __launch_bounds__(128) void final_kernel(
    const float* __restrict__ gamma_p, float* __restrict__ out)
{
    const int b = blockIdx.y;
    const int n = blockIdx.x * 128 + threadIdx.x;
    const int tid = threadIdx.x;

    __shared__ float sM[CQ][CO];   // 32 KB
    __shared__ float sVs[CO];
    __shared__ float sKs[CQ];

#pragma unroll
    for (int i = 0; i < 64; i++) {
        int idx = tid + i * 128;
        ((float*)sM)[idx] = g_matrix[(size_t)b * CQ * CO + idx];
    }
#pragma unroll
    for (int r = 0; r < 2; r++) {
        int c = tid + r * 128;
        sVs[c] = g_vsum[b * CO + c];
    }
    if (tid < CQ) sKs[tid] = g_ksum[b * CQ + tid];
    __syncthreads();

    float qn[CQ];
    float e = 0.0f;
#pragma unroll
    for (int q = 0; q < CQ; q++) {
        qn[q] = g_q[(size_t)(b * CQ + q) * HW + n];
        e += qn[q] * sKs[q];
    }
    const float tailor = 1.0f / fmaxf(NPOS + e, 1e-6f);
    const float gm = *gamma_p;

    for (int c0 = 0; c0 < CO; c0 += 4) {
        float4 a = *(const float4*)&sVs[c0];
#pragma unroll
        for (int q = 0; q < CQ; q++) {
            float4 m4 = *(const float4*)&sM[q][c0];
            a.x += qn[q] * m4.x;
            a.y += qn[q] * m4.y;
            a.z += qn[q] * m4.z;
            a.w += qn[q] * m4.w;
        }
        float r0 = fixnum(gm * a.x * tailor);
        float r1 = fixnum(gm * a.y * tailor);
        float r2 = fixnum(gm * a.z * tailor);
        float r3 = fixnum(gm * a.w * tailor);
        size_t base = (size_t)(b * CO + c0) * HW + n;
        out[base + 0 * HW] = r0 + __half2float(g_ff[base + 0 * HW]);
        out[base + 1 * HW] = r1 + __half2float(g_ff[base + 1 * HW]);
        out[base + 2 * HW] = r2 + __half2float(g_ff[base + 2 * HW]);
        out[base + 3 * HW] = r3 + __half2float(g_ff[base + 3 * HW]);
    }
}

// ---------------------------------------------------------------------------
extern "C" void kernel_launch(void* const* d_in, const int* in_sizes, int n_in,
                              void* d_out, int out_size)
{
    const float* s5 = (const float*)d_in[0];
    const float* s4 = (const float*)d_in[1];
    const float* s3 = (const float*)d_in[2];
    const float* s2 = (const float*)d_in[3];
    const float* w_conv   = (const float*)d_in[4];
    const float* bn_gamma = (const float*)d_in[5];
    const float* bn_beta  = (const float*)d_in[6];
    const float* wq = (const float*)d_in[7];
    const float* bq = (const float*)d_in[8];
    const float* wk = (const float*)d_in[9];
    const float* bk = (const float*)d_in[10];
    const float* wv = (const float*)d_in[11];
    const float* bv = (const float*)d_in[12];
    const float* gamma = (const float*)d_in[13];
    float* out = (float*)d_out;

    static int attr_done = 0;
    if (!attr_done) {
        cudaFuncSetAttribute(conv_gemm_mma, cudaFuncAttributeMaxDynamicSharedMemorySize, WTOT);
        cudaFuncSetAttribute(qkv_gemm_mma,  cudaFuncAttributeMaxDynamicSharedMemorySize, WTOT);
        attr_done = 1;
    }

    zero_kernel<<<64, 256>>>();
    convert_weights<<<1408, 256>>>(w_conv, wq, wk, wv);
    convert_inputs<<<65536, 256>>>(s5, s4, s3, s2);
    conv_gemm_mma<<<dim3(HW / 128, 2, BB), 128, WTOT>>>();
    bn_finalize<<<1, 256>>>();
    convert_feat<<<8192, 256>>>(bn_gamma, bn_beta);
    qkv_gemm_mma<<<dim3(HW / 128, 3, BB), 128, WTOT>>>(bq, bk, bv);
    normalize_qk<<<dim3(HW / 256, BB), 256>>>();
    matrix_kernel<<<dim3(32, CO / 64, BB), 256>>>();
    final_kernel<<<dim3(HW / 128, BB), 128>>>(gamma, out);
}